// round 1
// baseline (speedup 1.0000x reference)
#include <cuda_runtime.h>
#include <cstdint>

#define NN 4096
#define TT 8
#define KTOP 4
#define RR 8
#define DKK 64
#define BB 20

__device__ __align__(16) float g_q[NN * DKK];
__device__ __align__(16) float g_k[NN * DKK];
__device__ int g_ctx[NN * KTOP];
__device__ int g_rule[NN];

// ---------------------------------------------------------------------------
// Kernel A: q/k projections for context attention + rule argmax per node
// ---------------------------------------------------------------------------
__global__ __launch_bounds__(128) void kA(
    const float* __restrict__ obs, const float* __restrict__ obs_vel,
    const float* __restrict__ wq_rule, const float* __restrict__ bq_rule,
    const float* __restrict__ wq_ctx, const float* __restrict__ bq_ctx,
    const float* __restrict__ wk_ctx, const float* __restrict__ bk_ctx,
    const float* __restrict__ rule_emb)
{
    __shared__ float s_wq[32 * 64], s_wk[32 * 64], s_wr[16 * 64];
    __shared__ float s_bq[64], s_bk[64], s_br[64], s_emb[8 * 64];
    int tid = threadIdx.x;
    for (int i = tid; i < 32 * 64; i += 128) { s_wq[i] = wq_ctx[i]; s_wk[i] = wk_ctx[i]; }
    for (int i = tid; i < 16 * 64; i += 128) s_wr[i] = wq_rule[i];
    for (int i = tid; i < 64; i += 128) { s_bq[i] = bq_ctx[i]; s_bk[i] = bk_ctx[i]; s_br[i] = bq_rule[i]; }
    for (int i = tid; i < 8 * 64; i += 128) s_emb[i] = rule_emb[i];
    __syncthreads();

    int n = blockIdx.x * 128 + tid;
    // x_ctx[n, t*4+c]: c = [obs_s0, obs_s1, ov_s0, ov_s1]
    float x[32];
#pragma unroll
    for (int t = 0; t < TT; t++) {
        x[t * 4 + 0] = obs[0 * NN * TT + n * TT + t];
        x[t * 4 + 1] = obs[1 * NN * TT + n * TT + t];
        x[t * 4 + 2] = obs_vel[0 * NN * TT + n * TT + t];
        x[t * 4 + 3] = obs_vel[1 * NN * TT + n * TT + t];
    }
#pragma unroll 4
    for (int o = 0; o < 64; o++) {
        float aq = s_bq[o], ak = s_bk[o];
#pragma unroll
        for (int i = 0; i < 32; i++) {
            aq = fmaf(x[i], s_wq[i * 64 + o], aq);
            ak = fmaf(x[i], s_wk[i * 64 + o], ak);
        }
        g_q[n * 64 + o] = aq;
        g_k[n * 64 + o] = ak;
    }
    // rule logits: x_rule[t*2+s] = obs_vel[s][n][t] = x[t*4+2+s]
    float lg[8];
#pragma unroll
    for (int r = 0; r < 8; r++) lg[r] = 0.f;
#pragma unroll 4
    for (int o = 0; o < 64; o++) {
        float a = s_br[o];
#pragma unroll
        for (int t = 0; t < TT; t++) {
            a = fmaf(x[t * 4 + 2], s_wr[(t * 2 + 0) * 64 + o], a);
            a = fmaf(x[t * 4 + 3], s_wr[(t * 2 + 1) * 64 + o], a);
        }
#pragma unroll
        for (int r = 0; r < 8; r++) lg[r] = fmaf(a, s_emb[r * 64 + o], lg[r]);
    }
    int best = 0;
    float bv = lg[0];
#pragma unroll
    for (int r = 1; r < 8; r++)
        if (lg[r] > bv) { bv = lg[r]; best = r; }   // first-max == jnp.argmax
    g_rule[n] = best;
}

// ---------------------------------------------------------------------------
// Kernel B: scores = q @ k^T streamed, per-row top-4 (desc, ties -> lower idx)
// 16 rows/block, 256 blocks, 128-col smem tiles, packed f32x2 FMA.
// ---------------------------------------------------------------------------
__device__ __forceinline__ unsigned long long pack2(float a, float b) {
    unsigned long long r;
    asm("mov.b64 %0, {%1, %2};" : "=l"(r) : "f"(a), "f"(b));
    return r;
}
__device__ __forceinline__ void unpack2(unsigned long long v, float& a, float& b) {
    asm("mov.b64 {%0, %1}, %2;" : "=f"(a), "=f"(b) : "l"(v));
}
__device__ __forceinline__ unsigned long long fma2(unsigned long long a, unsigned long long b,
                                                   unsigned long long c) {
    unsigned long long d;
    asm("fma.rn.f32x2 %0, %1, %2, %3;" : "=l"(d) : "l"(a), "l"(b), "l"(c));
    return d;
}

__global__ __launch_bounds__(256) void kB()
{
    __shared__ unsigned long long q2_s[16 * 64];  // duplicated q pairs, 8KB
    __shared__ float k_s[64 * 128];               // 32KB; reused for candidate merge
    int tid = threadIdx.x;
    int ty = tid >> 5, tx = tid & 31;
    int row0 = blockIdx.x * 16;

    for (int i = tid; i < 16 * 64; i += 256) {
        float v = g_q[row0 * 64 + i];
        q2_s[i] = pack2(v, v);
    }

    float tv[2][4];
    int tix[2][4];
#pragma unroll
    for (int a = 0; a < 2; a++)
#pragma unroll
        for (int j = 0; j < 4; j++) { tv[a][j] = -3.4e38f; tix[a][j] = 0x7fffffff; }

    for (int ct = 0; ct < 32; ct++) {
        int c0 = ct * 128;
        __syncthreads();
        // load k tile transposed: k_s[kk][cl]
        for (int p = tid; p < 2048; p += 256) {
            int cl = p >> 4;
            int kkb = (p & 15) << 2;
            const float4 v = *reinterpret_cast<const float4*>(&g_k[(c0 + cl) * 64 + kkb]);
            k_s[(kkb + 0) * 128 + cl] = v.x;
            k_s[(kkb + 1) * 128 + cl] = v.y;
            k_s[(kkb + 2) * 128 + cl] = v.z;
            k_s[(kkb + 3) * 128 + cl] = v.w;
        }
        __syncthreads();

        unsigned long long acc00 = 0ull, acc01 = 0ull, acc10 = 0ull, acc11 = 0ull;
#pragma unroll 8
        for (int kk = 0; kk < 64; kk++) {
            const ulonglong2 kv = *reinterpret_cast<const ulonglong2*>(&k_s[kk * 128 + tx * 4]);
            unsigned long long q0 = q2_s[(ty) * 64 + kk];
            unsigned long long q1 = q2_s[(ty + 8) * 64 + kk];
            acc00 = fma2(q0, kv.x, acc00);
            acc01 = fma2(q0, kv.y, acc01);
            acc10 = fma2(q1, kv.x, acc10);
            acc11 = fma2(q1, kv.y, acc11);
        }
#pragma unroll
        for (int a = 0; a < 2; a++) {
            float v0, v1, v2, v3;
            unpack2(a == 0 ? acc00 : acc10, v0, v1);
            unpack2(a == 0 ? acc01 : acc11, v2, v3);
            float vals[4] = { v0, v1, v2, v3 };
#pragma unroll
            for (int c = 0; c < 4; c++) {
                float v = vals[c];
                int col = c0 + tx * 4 + c;
                if (v > tv[a][3] || (v == tv[a][3] && col < tix[a][3])) {
                    tv[a][3] = v; tix[a][3] = col;
#pragma unroll
                    for (int j = 3; j > 0; j--) {
                        bool sw = (tv[a][j] > tv[a][j - 1]) ||
                                  (tv[a][j] == tv[a][j - 1] && tix[a][j] < tix[a][j - 1]);
                        if (sw) {
                            float fv = tv[a][j]; tv[a][j] = tv[a][j - 1]; tv[a][j - 1] = fv;
                            int ii = tix[a][j]; tix[a][j] = tix[a][j - 1]; tix[a][j - 1] = ii;
                        }
                    }
                }
            }
        }
    }
    // merge: reuse k_s as candidate buffer: 16 rows * 32 tx * 4 (val + idx)
    __syncthreads();
    float* cv_ = k_s;
    int* ci_ = reinterpret_cast<int*>(k_s + 16 * 32 * 4);
#pragma unroll
    for (int a = 0; a < 2; a++) {
        int rl = ty + 8 * a;
        int base = (rl * 32 + tx) * 4;
#pragma unroll
        for (int j = 0; j < 4; j++) { cv_[base + j] = tv[a][j]; ci_[base + j] = tix[a][j]; }
    }
    __syncthreads();
    if (tid < 16) {
        float bvv[4]; int bii[4];
        for (int j = 0; j < 4; j++) { bvv[j] = -3.4e38f; bii[j] = 0x7fffffff; }
        int base = tid * 32 * 4;
        for (int p = 0; p < 128; p++) {
            float v = cv_[base + p];
            int col = ci_[base + p];
            if (v > bvv[3] || (v == bvv[3] && col < bii[3])) {
                bvv[3] = v; bii[3] = col;
                for (int j = 3; j > 0; j--) {
                    bool sw = (bvv[j] > bvv[j - 1]) || (bvv[j] == bvv[j - 1] && bii[j] < bii[j - 1]);
                    if (sw) {
                        float fv = bvv[j]; bvv[j] = bvv[j - 1]; bvv[j - 1] = fv;
                        int ii = bii[j]; bii[j] = bii[j - 1]; bii[j - 1] = ii;
                    }
                }
            }
        }
        for (int j = 0; j < 4; j++) g_ctx[(row0 + tid) * 4 + j] = bii[j];
    }
}

// ---------------------------------------------------------------------------
// Kernel C: gather ctx neighbors + selected-rule conv pipeline per (n, b).
// 8 nodes x 20 noise samples per block; all 8 rules' weights staged in smem
// with bank-padded strides.
// ---------------------------------------------------------------------------
#define CPY(dst, src, n_) for (int _i = tid; _i < (n_); _i += 160) (dst)[_i] = (src)[_i];
#define CPYP(dst, src, per, stride) \
    for (int _i = tid; _i < 8 * (per); _i += 160) (dst)[(_i / (per)) * (stride) + (_i % (per))] = (src)[_i];

__global__ __launch_bounds__(160) void kC(
    const float* __restrict__ obs_vel, const float* __restrict__ noise,
    const float* __restrict__ w_noise, const float* __restrict__ w_indiv,
    const float* __restrict__ w_social,
    const float* __restrict__ sp_w, const float* __restrict__ sp_b,
    const float* __restrict__ spr_w, const float* __restrict__ spr_b,
    const float* __restrict__ tp_w, const float* __restrict__ tp_b,
    const float* __restrict__ tpr_w, const float* __restrict__ tpr_b,
    const float* __restrict__ spi_w, const float* __restrict__ spi_b,
    const float* __restrict__ spir_w, const float* __restrict__ spir_b,
    const float* __restrict__ tpi_w, const float* __restrict__ tpi_b,
    const float* __restrict__ tpir_w, const float* __restrict__ tpir_b,
    float* __restrict__ out)
{
    __shared__ float s_sp_w[8 * 60], s_sp_b[8 * 2], s_spr_w[8 * 20], s_spr_b[8 * 2];
    __shared__ float s_tp_w[8 * 289], s_tp_b[8 * 12], s_tpr_w[8 * 97], s_tpr_b[8 * 12];
    __shared__ float s_spi_w[8 * 12], s_spi_b[8 * 2], s_spir_w[8 * 4], s_spir_b[8 * 2];
    __shared__ float s_tpi_w[8 * 289], s_tpi_b[8 * 12], s_tpir_w[8 * 97], s_tpir_b[8 * 12];
    __shared__ float s_wn[8], s_wi[8], s_ws[8];
    __shared__ float s_noise[BB * 2];
    __shared__ float s_ov[8 * 16];   // [node][s][t]
    __shared__ float s_cvx[8 * 64];  // [node][k][s][t]
    __shared__ int s_rule[8];

    int tid = threadIdx.x;
    int n0 = blockIdx.x * 8;

    CPY(s_sp_w, sp_w, 8 * 60) CPY(s_sp_b, sp_b, 16) CPY(s_spr_w, spr_w, 8 * 20) CPY(s_spr_b, spr_b, 16)
    CPYP(s_tp_w, tp_w, 288, 289) CPY(s_tp_b, tp_b, 96) CPYP(s_tpr_w, tpr_w, 96, 97) CPY(s_tpr_b, tpr_b, 96)
    CPY(s_spi_w, spi_w, 8 * 12) CPY(s_spi_b, spi_b, 16) CPY(s_spir_w, spir_w, 32) CPY(s_spir_b, spir_b, 16)
    CPYP(s_tpi_w, tpi_w, 288, 289) CPY(s_tpi_b, tpi_b, 96) CPYP(s_tpir_w, tpir_w, 96, 97) CPY(s_tpir_b, tpir_b, 96)
    CPY(s_wn, w_noise, 8) CPY(s_wi, w_indiv, 8) CPY(s_ws, w_social, 8)
    CPY(s_noise, noise, BB * 2)

    for (int i = tid; i < 8 * 16; i += 160) {
        int node = i >> 4, s = (i >> 3) & 1, t = i & 7;
        s_ov[i] = obs_vel[s * NN * TT + (n0 + node) * TT + t];
    }
    for (int i = tid; i < 8 * 64; i += 160) {
        int node = i >> 6, rem = i & 63, k = rem >> 4, s = (rem >> 3) & 1, t = rem & 7;
        int nb = g_ctx[(n0 + node) * 4 + k];
        s_cvx[i] = obs_vel[s * NN * TT + nb * TT + t];
    }
    if (tid < 8) s_rule[tid] = g_rule[n0 + tid];
    __syncthreads();

    int node = tid / 20, b = tid - node * 20;
    int n = n0 + node;
    int r = s_rule[node];
    float wn = s_wn[r], wi = s_wi[r], ws = s_ws[r];
    float nz0 = s_noise[b * 2 + 0] * wn;
    float nz1 = s_noise[b * 2 + 1] * wn;

    // comb[ci][t]: ci 0..1 = own vel, ci 2..9 = (k,s) neighbor vel; noise added
    float comb[10][8];
#pragma unroll
    for (int t = 0; t < 8; t++) {
        comb[0][t] = s_ov[node * 16 + t] + nz0;
        comb[1][t] = s_ov[node * 16 + 8 + t] + nz1;
    }
#pragma unroll
    for (int k = 0; k < 4; k++)
#pragma unroll
        for (int s = 0; s < 2; s++)
#pragma unroll
            for (int t = 0; t < 8; t++)
                comb[2 + k * 2 + s][t] = s_cvx[node * 64 + k * 16 + s * 8 + t] + (s == 0 ? nz0 : nz1);

    // --- si = relu(conv3(ov)+b) + conv1(ov)+b  (2 in-ch) ---
    const float* pw3 = s_spi_w + r * 12;   // [s*6 + ci*3 + j]
    const float* pw1 = s_spir_w + r * 4;   // [s*2 + ci]
    float si[2][8];
#pragma unroll
    for (int s = 0; s < 2; s++) {
        float b3 = s_spi_b[r * 2 + s], b1 = s_spir_b[r * 2 + s];
#pragma unroll
        for (int t = 0; t < 8; t++) {
            float a = b3;
#pragma unroll
            for (int ci = 0; ci < 2; ci++) {
                if (t > 0) a = fmaf(pw3[s * 6 + ci * 3 + 0], comb[ci][t - 1], a);
                a = fmaf(pw3[s * 6 + ci * 3 + 1], comb[ci][t], a);
                if (t < 7) a = fmaf(pw3[s * 6 + ci * 3 + 2], comb[ci][t + 1], a);
            }
            a = fmaxf(a, 0.f);
            float c1 = b1;
#pragma unroll
            for (int ci = 0; ci < 2; ci++) c1 = fmaf(pw1[s * 2 + ci], comb[ci][t], c1);
            si[s][t] = a + c1;
        }
    }

    // --- ss = relu(conv3(comb)+b) + conv1(comb)+b  (10 in-ch) ---
    const float* qw3 = s_sp_w + r * 60;    // [s*30 + ci*3 + j]
    const float* qw1 = s_spr_w + r * 20;   // [s*10 + ci]
    float ssv[2][8];
#pragma unroll
    for (int s = 0; s < 2; s++) {
        float b3 = s_sp_b[r * 2 + s], b1 = s_spr_b[r * 2 + s];
#pragma unroll
        for (int t = 0; t < 8; t++) {
            float a = b3;
#pragma unroll
            for (int ci = 0; ci < 10; ci++) {
                if (t > 0) a = fmaf(qw3[s * 30 + ci * 3 + 0], comb[ci][t - 1], a);
                a = fmaf(qw3[s * 30 + ci * 3 + 1], comb[ci][t], a);
                if (t < 7) a = fmaf(qw3[s * 30 + ci * 3 + 2], comb[ci][t + 1], a);
            }
            a = fmaxf(a, 0.f);
            float c1 = b1;
#pragma unroll
            for (int ci = 0; ci < 10; ci++) c1 = fmaf(qw1[s * 10 + ci], comb[ci][t], c1);
            ssv[s][t] = a + c1;
        }
    }

    // --- time convs: channels = T (8), length = S (2), pad 1 ---
    const float* wtp = s_tp_w + r * 289;    // [(o*8+c)*3 + j]
    const float* wtpr = s_tpr_w + r * 97;   // [o*8+c]
    const float* wti = s_tpi_w + r * 289;
    const float* wtir = s_tpir_w + r * 97;
    float* outp = out + ((size_t)b * NN + n) * 24;
#pragma unroll
    for (int o = 0; o < 12; o++) {
        float i0 = s_tpi_b[r * 12 + o] + s_tpir_b[r * 12 + o];
        float i1 = i0;
        float s0 = s_tp_b[r * 12 + o] + s_tpr_b[r * 12 + o];
        float s1 = s0;
#pragma unroll
        for (int c = 0; c < 8; c++) {
            float w0 = wti[(o * 8 + c) * 3 + 0], w1 = wti[(o * 8 + c) * 3 + 1], w2 = wti[(o * 8 + c) * 3 + 2];
            float wr = wtir[o * 8 + c];
            i0 = fmaf(w1, si[0][c], i0); i0 = fmaf(w2, si[1][c], i0); i0 = fmaf(wr, si[0][c], i0);
            i1 = fmaf(w0, si[0][c], i1); i1 = fmaf(w1, si[1][c], i1); i1 = fmaf(wr, si[1][c], i1);
            float u0 = wtp[(o * 8 + c) * 3 + 0], u1 = wtp[(o * 8 + c) * 3 + 1], u2 = wtp[(o * 8 + c) * 3 + 2];
            float ur = wtpr[o * 8 + c];
            s0 = fmaf(u1, ssv[0][c], s0); s0 = fmaf(u2, ssv[1][c], s0); s0 = fmaf(ur, ssv[0][c], s0);
            s1 = fmaf(u0, ssv[0][c], s1); s1 = fmaf(u1, ssv[1][c], s1); s1 = fmaf(ur, ssv[1][c], s1);
        }
        outp[o * 2 + 0] = wi * i0 + ws * s0;
        outp[o * 2 + 1] = wi * i1 + ws * s1;
    }
}

// ---------------------------------------------------------------------------
extern "C" void kernel_launch(void* const* d_in, const int* in_sizes, int n_in,
                              void* d_out, int out_size)
{
    const float* obs      = (const float*)d_in[0];
    const float* obs_vel  = (const float*)d_in[1];
    const float* noise    = (const float*)d_in[2];
    const float* wq_rule  = (const float*)d_in[3];
    const float* bq_rule  = (const float*)d_in[4];
    const float* wq_ctx   = (const float*)d_in[5];
    const float* bq_ctx   = (const float*)d_in[6];
    const float* wk_ctx   = (const float*)d_in[7];
    const float* bk_ctx   = (const float*)d_in[8];
    const float* rule_emb = (const float*)d_in[9];
    const float* w_noise  = (const float*)d_in[10];
    const float* w_indiv  = (const float*)d_in[11];
    const float* w_social = (const float*)d_in[12];
    const float* sp_w  = (const float*)d_in[13];
    const float* sp_b  = (const float*)d_in[14];
    const float* spr_w = (const float*)d_in[15];
    const float* spr_b = (const float*)d_in[16];
    const float* tp_w  = (const float*)d_in[17];
    const float* tp_b  = (const float*)d_in[18];
    const float* tpr_w = (const float*)d_in[19];
    const float* tpr_b = (const float*)d_in[20];
    const float* spi_w  = (const float*)d_in[21];
    const float* spi_b  = (const float*)d_in[22];
    const float* spir_w = (const float*)d_in[23];
    const float* spir_b = (const float*)d_in[24];
    const float* tpi_w  = (const float*)d_in[25];
    const float* tpi_b  = (const float*)d_in[26];
    const float* tpir_w = (const float*)d_in[27];
    const float* tpir_b = (const float*)d_in[28];
    float* out = (float*)d_out;

    kA<<<32, 128>>>(obs, obs_vel, wq_rule, bq_rule, wq_ctx, bq_ctx, wk_ctx, bk_ctx, rule_emb);
    kB<<<256, 256>>>();
    kC<<<512, 160>>>(obs_vel, noise, w_noise, w_indiv, w_social,
                     sp_w, sp_b, spr_w, spr_b, tp_w, tp_b, tpr_w, tpr_b,
                     spi_w, spi_b, spir_w, spir_b, tpi_w, tpi_b, tpir_w, tpir_b, out);
}

// round 2
// speedup vs baseline: 1.1913x; 1.1913x over previous
#include <cuda_runtime.h>
#include <cstdint>

#define NN 4096
#define TT 8
#define KTOP 4
#define RR 8
#define DKK 64
#define BB 20

typedef unsigned long long ull;

__device__ __align__(16) float g_q[NN * DKK];
__device__ __align__(16) float g_k[NN * DKK];
__device__ __align__(16) float g_rq[NN * DKK];
__device__ __align__(16) float g_C[RR * 24 * 36];
__device__ int g_ctx[NN * KTOP];
__device__ int g_rule[NN];

__device__ __forceinline__ ull pack2(float a, float b) {
    ull r;
    asm("mov.b64 %0, {%1, %2};" : "=l"(r) : "f"(a), "f"(b));
    return r;
}
__device__ __forceinline__ void unpack2(ull v, float& a, float& b) {
    asm("mov.b64 {%0, %1}, %2;" : "=f"(a), "=f"(b) : "l"(v));
}
__device__ __forceinline__ ull fma2(ull a, ull b, ull c) {
    ull d;
    asm("fma.rn.f32x2 %0, %1, %2, %3;" : "=l"(d) : "l"(a), "l"(b), "l"(c));
    return d;
}

// top-4 insert: value desc, ties -> lower index (matches lax.top_k)
__device__ __forceinline__ void ins4(float v, int idx, float* tv, int* ti) {
    if (v > tv[3] || (v == tv[3] && idx < ti[3])) {
        tv[3] = v; ti[3] = idx;
#pragma unroll
        for (int j = 3; j > 0; j--) {
            bool sw = (tv[j] > tv[j - 1]) || (tv[j] == tv[j - 1] && ti[j] < ti[j - 1]);
            if (sw) {
                float f = tv[j]; tv[j] = tv[j - 1]; tv[j - 1] = f;
                int q = ti[j]; ti[j] = ti[j - 1]; ti[j - 1] = q;
            }
        }
    }
}

// ---------------------------------------------------------------------------
// kA: x[4096x32] @ W[32x192] -> g_q | g_k | g_rq  (rule proj zero-padded)
// 64 blocks x 256 thr. Block tile 64 rows x 192 cols. Thread 8 rows x 6 cols.
// ---------------------------------------------------------------------------
__global__ __launch_bounds__(256) void kA(
    const float* __restrict__ obs, const float* __restrict__ obs_vel,
    const float* __restrict__ wq_rule, const float* __restrict__ bq_rule,
    const float* __restrict__ wq_ctx, const float* __restrict__ bq_ctx,
    const float* __restrict__ wk_ctx, const float* __restrict__ bk_ctx)
{
    __shared__ __align__(16) ull x2_s[32 * 64];  // [i][node], dup pairs
    __shared__ __align__(16) ull w_s[32 * 96];   // [i][colpair]
    int tid = threadIdx.x;
    int n0 = blockIdx.x * 64;

    // stage x
    float* xf = (float*)x2_s;
    for (int e = tid; e < 32 * 64; e += 256) {
        int i = e >> 6, node = e & 63;
        int t = i >> 2, c = i & 3;
        const float* src = (c < 2) ? obs : obs_vel;
        float v = src[(c & 1) * NN * TT + (n0 + node) * TT + t];
        xf[e * 2] = v; xf[e * 2 + 1] = v;
    }
    // stage W (cols: 0..63 q, 64..127 k, 128..191 rq zero-padded)
    float* wf = (float*)w_s;
    for (int e = tid; e < 32 * 192; e += 256) {
        int i = e / 192, col = e % 192;
        float v;
        if (col < 64) v = wq_ctx[i * 64 + col];
        else if (col < 128) v = wk_ctx[i * 64 + col - 64];
        else {
            int c = i & 3;
            if (c >= 2) v = wq_rule[((i >> 2) * 2 + (c - 2)) * 64 + (col - 128)];
            else v = 0.f;
        }
        wf[i * 192 + col] = v;
    }
    __syncthreads();

    int w = tid >> 5, tx = tid & 31;
    int rbase = w * 8;
    // bias pairs for this thread's 3 colpairs
    ull bp[3];
#pragma unroll
    for (int j = 0; j < 3; j++) {
        int c2 = (tx * 3 + j) * 2;
        float b0, b1;
        if (c2 < 64) { b0 = bq_ctx[c2]; b1 = bq_ctx[c2 + 1]; }
        else if (c2 < 128) { b0 = bk_ctx[c2 - 64]; b1 = bk_ctx[c2 - 63]; }
        else { b0 = bq_rule[c2 - 128]; b1 = bq_rule[c2 - 127]; }
        bp[j] = pack2(b0, b1);
    }
    ull acc[8][3];
#pragma unroll
    for (int r = 0; r < 8; r++)
#pragma unroll
        for (int j = 0; j < 3; j++) acc[r][j] = bp[j];

#pragma unroll 8
    for (int kk = 0; kk < 32; kk++) {
        const ulonglong2* qp = (const ulonglong2*)(x2_s + kk * 64 + rbase);
        ulonglong2 q0 = qp[0], q1 = qp[1], q2v = qp[2], q3 = qp[3];
        ull qr[8] = { q0.x, q0.y, q1.x, q1.y, q2v.x, q2v.y, q3.x, q3.y };
        ull wv0 = w_s[kk * 96 + tx * 3 + 0];
        ull wv1 = w_s[kk * 96 + tx * 3 + 1];
        ull wv2 = w_s[kk * 96 + tx * 3 + 2];
#pragma unroll
        for (int r = 0; r < 8; r++) {
            acc[r][0] = fma2(qr[r], wv0, acc[r][0]);
            acc[r][1] = fma2(qr[r], wv1, acc[r][1]);
            acc[r][2] = fma2(qr[r], wv2, acc[r][2]);
        }
    }
#pragma unroll
    for (int r = 0; r < 8; r++) {
        int node = n0 + rbase + r;
#pragma unroll
        for (int j = 0; j < 3; j++) {
            int c2 = (tx * 3 + j) * 2;
            float v0, v1;
            unpack2(acc[r][j], v0, v1);
            float* dst = (c2 < 64) ? g_q : (c2 < 128) ? g_k : g_rq;
            int cc = c2 & 63;
            dst[node * 64 + cc] = v0;
            dst[node * 64 + cc + 1] = v1;
        }
    }
}

// ---------------------------------------------------------------------------
// kR: rule argmax from g_rq @ rule_emb^T
// ---------------------------------------------------------------------------
__global__ __launch_bounds__(128) void kR(const float* __restrict__ rule_emb)
{
    __shared__ float s_emb[64 * 8];  // [o][r]
    int tid = threadIdx.x;
    for (int e = tid; e < 512; e += 128) s_emb[e] = rule_emb[(e & 7) * 64 + (e >> 3)];
    __syncthreads();
    int n = blockIdx.x * 128 + tid;
    float lg[8];
#pragma unroll
    for (int r = 0; r < 8; r++) lg[r] = 0.f;
#pragma unroll
    for (int og = 0; og < 16; og++) {
        float4 v = *(const float4*)&g_rq[n * 64 + og * 4];
        float vv[4] = { v.x, v.y, v.z, v.w };
#pragma unroll
        for (int e = 0; e < 4; e++) {
            int o = og * 4 + e;
#pragma unroll
            for (int r = 0; r < 8; r++) lg[r] = fmaf(vv[e], s_emb[o * 8 + r], lg[r]);
        }
    }
    int best = 0;
    float bv = lg[0];
#pragma unroll
    for (int r = 1; r < 8; r++)
        if (lg[r] > bv) { bv = lg[r]; best = r; }
    g_rule[n] = best;
}

// ---------------------------------------------------------------------------
// kB: scores = q @ k^T + per-row top-4.
// 128 blocks x 256 thr. Block: 32 rows, col tiles of 256, kk=64 in smem.
// Warp = 4 rows x 256 cols; thread = 4 rows x 8 cols. Packed f32x2.
// Dynamic smem: k2[64][128] ull (64KB) + q2[64][32] ull (16KB) = 80KB.
// ---------------------------------------------------------------------------
__global__ __launch_bounds__(256, 1) void kB()
{
    extern __shared__ __align__(16) ull dsm[];
    ull* k2 = dsm;            // [kk][colpair]
    ull* q2 = dsm + 64 * 128; // [kk][row] (dup pairs)
    int tid = threadIdx.x;
    int w = tid >> 5, tx = tid & 31;
    int row0 = blockIdx.x * 32;
    int r0 = w * 4;

    // stage q2 (dup)
    {
        int row = tid & 31, kkb = (tid >> 5) * 8;
        const float4* src = (const float4*)&g_q[(row0 + row) * 64 + kkb];
        float4 a = src[0], b = src[1];
        float vv[8] = { a.x, a.y, a.z, a.w, b.x, b.y, b.z, b.w };
#pragma unroll
        for (int e = 0; e < 8; e++) q2[(kkb + e) * 32 + row] = pack2(vv[e], vv[e]);
    }

    float tv[4][4];
    int ti[4][4];
#pragma unroll
    for (int r = 0; r < 4; r++)
#pragma unroll
        for (int j = 0; j < 4; j++) { tv[r][j] = -3.4e38f; ti[r][j] = 0x7fffffff; }

    int cp = tid & 127, half = tid >> 7;
    float* kf = (float*)k2;

    for (int ct = 0; ct < 16; ct++) {
        int c0 = ct * 256;
        __syncthreads();
        {
            const float4* src = (const float4*)(g_k + (size_t)(c0 + cp * 2 + half) * 64);
#pragma unroll
            for (int kb = 0; kb < 16; kb++) {
                float4 v = src[kb];
                int base = (kb * 4) * 256 + cp * 2 + half;
                kf[base] = v.x;
                kf[base + 256] = v.y;
                kf[base + 512] = v.z;
                kf[base + 768] = v.w;
            }
        }
        __syncthreads();

        ull acc[4][4];
#pragma unroll
        for (int r = 0; r < 4; r++)
#pragma unroll
            for (int j = 0; j < 4; j++) acc[r][j] = 0ull;

#pragma unroll 8
        for (int kk = 0; kk < 64; kk++) {
            const ulonglong2* qp = (const ulonglong2*)(q2 + kk * 32 + r0);
            ulonglong2 qa = qp[0], qb = qp[1];
            const ulonglong2* kp = (const ulonglong2*)(k2 + kk * 128 + tx * 4);
            ulonglong2 ka = kp[0], kb = kp[1];
            ull kv[4] = { ka.x, ka.y, kb.x, kb.y };
            ull qr[4] = { qa.x, qa.y, qb.x, qb.y };
#pragma unroll
            for (int r = 0; r < 4; r++) {
                acc[r][0] = fma2(qr[r], kv[0], acc[r][0]);
                acc[r][1] = fma2(qr[r], kv[1], acc[r][1]);
                acc[r][2] = fma2(qr[r], kv[2], acc[r][2]);
                acc[r][3] = fma2(qr[r], kv[3], acc[r][3]);
            }
        }
#pragma unroll
        for (int r = 0; r < 4; r++)
#pragma unroll
            for (int j = 0; j < 4; j++) {
                float v0, v1;
                unpack2(acc[r][j], v0, v1);
                int col = c0 + tx * 8 + j * 2;
                ins4(v0, col, tv[r], ti[r]);
                ins4(v1, col + 1, tv[r], ti[r]);
            }
    }
    // block-wide merge (overlay k2 area as scratch)
    __syncthreads();
    float* scv = (float*)dsm;
    int* sci = (int*)(scv + 32 * 32 * 4);
#pragma unroll
    for (int r = 0; r < 4; r++)
#pragma unroll
        for (int j = 0; j < 4; j++) {
            int e = ((r0 + r) * 32 + tx) * 4 + j;
            scv[e] = tv[r][j];
            sci[e] = ti[r][j];
        }
    __syncthreads();
    if (tx < 4) {
        int row = r0 + tx;
        float bvv[4]; int bii[4];
#pragma unroll
        for (int j = 0; j < 4; j++) { bvv[j] = -3.4e38f; bii[j] = 0x7fffffff; }
        int base = row * 128;
        for (int p = 0; p < 128; p++) ins4(scv[base + p], sci[base + p], bvv, bii);
#pragma unroll
        for (int j = 0; j < 4; j++) g_ctx[(row0 + row) * 4 + j] = bii[j];
    }
}

// ---------------------------------------------------------------------------
// kP: precompute rule-combined time-conv matrices C[r][24][36]
//     out[o2] = C[o2][0..31] . (si0|si1|ss0|ss1) + C[o2][32]
// ---------------------------------------------------------------------------
__global__ void kP(
    const float* __restrict__ w_indiv, const float* __restrict__ w_social,
    const float* __restrict__ tp_w, const float* __restrict__ tp_b,
    const float* __restrict__ tpr_w, const float* __restrict__ tpr_b,
    const float* __restrict__ tpi_w, const float* __restrict__ tpi_b,
    const float* __restrict__ tpir_w, const float* __restrict__ tpir_b)
{
    int t = threadIdx.x;
    if (t >= 192) return;
    int r = t / 24, o2 = t % 24, o = o2 >> 1, pos = o2 & 1;
    float wi = w_indiv[r], ws = w_social[r];
    float* dst = g_C + (r * 24 + o2) * 36;
#pragma unroll
    for (int c = 0; c < 8; c++) {
        int wb = (r * 12 + o) * 8 + c;
        const float* wt = tpi_w + wb * 3;
        float wri = tpir_w[wb];
        float ci0 = pos == 0 ? (wt[1] + wri) : wt[0];
        float ci1 = pos == 0 ? wt[2] : (wt[1] + wri);
        dst[c] = wi * ci0;
        dst[8 + c] = wi * ci1;
        const float* ut = tp_w + wb * 3;
        float urs = tpr_w[wb];
        float cs0 = pos == 0 ? (ut[1] + urs) : ut[0];
        float cs1 = pos == 0 ? ut[2] : (ut[1] + urs);
        dst[16 + c] = ws * cs0;
        dst[24 + c] = ws * cs1;
    }
    dst[32] = wi * (tpi_b[r * 12 + o] + tpir_b[r * 12 + o])
            + ws * (tp_b[r * 12 + o] + tpr_b[r * 12 + o]);
    dst[33] = 0.f; dst[34] = 0.f; dst[35] = 0.f;
}

// ---------------------------------------------------------------------------
// kC: gather + selected-rule spatial convs + combined matvec. 8 nodes x 20 b.
// ---------------------------------------------------------------------------
__global__ __launch_bounds__(160) void kC(
    const float* __restrict__ obs_vel, const float* __restrict__ noise,
    const float* __restrict__ w_noise,
    const float* __restrict__ sp_w, const float* __restrict__ sp_b,
    const float* __restrict__ spr_w, const float* __restrict__ spr_b,
    const float* __restrict__ spi_w, const float* __restrict__ spi_b,
    const float* __restrict__ spir_w, const float* __restrict__ spir_b,
    float* __restrict__ out)
{
    __shared__ __align__(16) float s_C[8 * 24 * 36];
    __shared__ float s_sp_w[480], s_sp_b[16], s_spr_w[160], s_spr_b[16];
    __shared__ float s_spi_w[96], s_spi_b[16], s_spir_w[32], s_spir_b[16];
    __shared__ float s_wn[8], s_noise[BB * 2];
    __shared__ float s_ov[128], s_cvx[512];
    __shared__ int s_rule[8];

    int tid = threadIdx.x;
    int n0 = blockIdx.x * 8;

    for (int i = tid; i < 8 * 24 * 36; i += 160) s_C[i] = g_C[i];
    for (int i = tid; i < 480; i += 160) s_sp_w[i] = sp_w[i];
    for (int i = tid; i < 160; i += 160) s_spr_w[i] = spr_w[i];
    if (tid < 96) s_spi_w[tid] = spi_w[tid];
    if (tid < 32) s_spir_w[tid] = spir_w[tid];
    if (tid < 16) {
        s_sp_b[tid] = sp_b[tid]; s_spr_b[tid] = spr_b[tid];
        s_spi_b[tid] = spi_b[tid]; s_spir_b[tid] = spir_b[tid];
    }
    if (tid < 8) { s_wn[tid] = w_noise[tid]; s_rule[tid] = g_rule[n0 + tid]; }
    if (tid < 40) s_noise[tid] = noise[tid];
    for (int i = tid; i < 128; i += 160) {
        int node = i >> 4, s = (i >> 3) & 1, t = i & 7;
        s_ov[i] = obs_vel[s * NN * TT + (n0 + node) * TT + t];
    }
    for (int i = tid; i < 512; i += 160) {
        int node = i >> 6, rem = i & 63, k = rem >> 4, s = (rem >> 3) & 1, t = rem & 7;
        int nb = g_ctx[(n0 + node) * 4 + k];
        s_cvx[i] = obs_vel[s * NN * TT + nb * TT + t];
    }
    __syncthreads();

    int node = tid / 20, b = tid - node * 20;
    int n = n0 + node;
    int r = s_rule[node];
    float wn = s_wn[r];
    float nz0 = s_noise[b * 2 + 0] * wn;
    float nz1 = s_noise[b * 2 + 1] * wn;

    float v0[8], v1[8];
#pragma unroll
    for (int t = 0; t < 8; t++) {
        v0[t] = s_ov[node * 16 + t] + nz0;
        v1[t] = s_ov[node * 16 + 8 + t] + nz1;
    }

    float vals[32];  // si0 | si1 | ss0 | ss1

    // ---- indiv spatial path (2 channels) ----
    {
        const float* pw3 = s_spi_w + r * 12;
        const float* pw1 = s_spir_w + r * 4;
#pragma unroll
        for (int so = 0; so < 2; so++) {
            float b3 = s_spi_b[r * 2 + so], b1 = s_spir_b[r * 2 + so];
            float w00 = pw3[so * 6 + 0], w01 = pw3[so * 6 + 1], w02 = pw3[so * 6 + 2];
            float w10 = pw3[so * 6 + 3], w11 = pw3[so * 6 + 4], w12 = pw3[so * 6 + 5];
            float wr0 = pw1[so * 2 + 0], wr1 = pw1[so * 2 + 1];
#pragma unroll
            for (int t = 0; t < 8; t++) {
                float a = b3;
                a = fmaf(w01, v0[t], a);
                a = fmaf(w11, v1[t], a);
                if (t > 0) { a = fmaf(w00, v0[t - 1], a); a = fmaf(w10, v1[t - 1], a); }
                if (t < 7) { a = fmaf(w02, v0[t + 1], a); a = fmaf(w12, v1[t + 1], a); }
                a = fmaxf(a, 0.f);
                float c1 = b1;
                c1 = fmaf(wr0, v0[t], c1);
                c1 = fmaf(wr1, v1[t], c1);
                vals[so * 8 + t] = a + c1;
            }
        }
    }

    // ---- social spatial path (10 channels, streamed) ----
    {
        float a0[8], a1[8], c0[8], c1[8];
        float ba0 = s_sp_b[r * 2], ba1 = s_sp_b[r * 2 + 1];
        float bc0 = s_spr_b[r * 2], bc1 = s_spr_b[r * 2 + 1];
#pragma unroll
        for (int t = 0; t < 8; t++) { a0[t] = ba0; a1[t] = ba1; c0[t] = bc0; c1[t] = bc1; }
        const float* q3 = s_sp_w + r * 60;
        const float* q1 = s_spr_w + r * 20;

#define PROC_CH(ci, VV)                                                        \
        {                                                                      \
            float u0 = q3[(ci) * 3], u1 = q3[(ci) * 3 + 1], u2 = q3[(ci) * 3 + 2]; \
            float z0 = q3[30 + (ci) * 3], z1 = q3[30 + (ci) * 3 + 1], z2 = q3[30 + (ci) * 3 + 2]; \
            float ur = q1[(ci)], zr = q1[10 + (ci)];                           \
            _Pragma("unroll")                                                  \
            for (int t = 0; t < 8; t++) {                                      \
                float x = VV[t];                                               \
                a0[t] = fmaf(u1, x, a0[t]); a1[t] = fmaf(z1, x, a1[t]);        \
                c0[t] = fmaf(ur, x, c0[t]); c1[t] = fmaf(zr, x, c1[t]);        \
                if (t > 0) { a0[t] = fmaf(u0, VV[t - 1], a0[t]); a1[t] = fmaf(z0, VV[t - 1], a1[t]); } \
                if (t < 7) { a0[t] = fmaf(u2, VV[t + 1], a0[t]); a1[t] = fmaf(z2, VV[t + 1], a1[t]); } \
            }                                                                  \
        }

        PROC_CH(0, v0)
        PROC_CH(1, v1)
#pragma unroll
        for (int k = 0; k < 4; k++) {
            float nb0[8], nb1[8];
#pragma unroll
            for (int t = 0; t < 8; t++) {
                nb0[t] = s_cvx[node * 64 + k * 16 + t] + nz0;
                nb1[t] = s_cvx[node * 64 + k * 16 + 8 + t] + nz1;
            }
            PROC_CH(2 + k * 2 + 0, nb0)
            PROC_CH(2 + k * 2 + 1, nb1)
        }
#undef PROC_CH
#pragma unroll
        for (int t = 0; t < 8; t++) {
            vals[16 + t] = fmaxf(a0[t], 0.f) + c0[t];
            vals[24 + t] = fmaxf(a1[t], 0.f) + c1[t];
        }
    }

    // pack pairs for fma2 matvec
    ull pk[16];
#pragma unroll
    for (int p = 0; p < 16; p++) pk[p] = pack2(vals[2 * p], vals[2 * p + 1]);

    const float* Cb = s_C + r * 24 * 36;
    float* outp = out + ((size_t)b * NN + n) * 24;
#pragma unroll 4
    for (int o2 = 0; o2 < 24; o2++) {
        const ulonglong2* cp = (const ulonglong2*)(Cb + o2 * 36);
        ull acc = pack2(Cb[o2 * 36 + 32], 0.f);
#pragma unroll
        for (int p = 0; p < 8; p++) {
            ulonglong2 cc = cp[p];
            acc = fma2(cc.x, pk[2 * p], acc);
            acc = fma2(cc.y, pk[2 * p + 1], acc);
        }
        float lo, hi;
        unpack2(acc, lo, hi);
        outp[o2] = lo + hi;
    }
}

// ---------------------------------------------------------------------------
extern "C" void kernel_launch(void* const* d_in, const int* in_sizes, int n_in,
                              void* d_out, int out_size)
{
    const float* obs      = (const float*)d_in[0];
    const float* obs_vel  = (const float*)d_in[1];
    const float* noise    = (const float*)d_in[2];
    const float* wq_rule  = (const float*)d_in[3];
    const float* bq_rule  = (const float*)d_in[4];
    const float* wq_ctx   = (const float*)d_in[5];
    const float* bq_ctx   = (const float*)d_in[6];
    const float* wk_ctx   = (const float*)d_in[7];
    const float* bk_ctx   = (const float*)d_in[8];
    const float* rule_emb = (const float*)d_in[9];
    const float* w_noise  = (const float*)d_in[10];
    const float* w_indiv  = (const float*)d_in[11];
    const float* w_social = (const float*)d_in[12];
    const float* sp_w  = (const float*)d_in[13];
    const float* sp_b  = (const float*)d_in[14];
    const float* spr_w = (const float*)d_in[15];
    const float* spr_b = (const float*)d_in[16];
    const float* tp_w  = (const float*)d_in[17];
    const float* tp_b  = (const float*)d_in[18];
    const float* tpr_w = (const float*)d_in[19];
    const float* tpr_b = (const float*)d_in[20];
    const float* spi_w  = (const float*)d_in[21];
    const float* spi_b  = (const float*)d_in[22];
    const float* spir_w = (const float*)d_in[23];
    const float* spir_b = (const float*)d_in[24];
    const float* tpi_w  = (const float*)d_in[25];
    const float* tpi_b  = (const float*)d_in[26];
    const float* tpir_w = (const float*)d_in[27];
    const float* tpir_b = (const float*)d_in[28];
    float* out = (float*)d_out;

    static bool attr_set = false;
    if (!attr_set) {
        cudaFuncSetAttribute(kB, cudaFuncAttributeMaxDynamicSharedMemorySize, 80 * 1024);
        attr_set = true;
    }

    kA<<<64, 256>>>(obs, obs_vel, wq_rule, bq_rule, wq_ctx, bq_ctx, wk_ctx, bk_ctx);
    kR<<<32, 128>>>(rule_emb);
    kP<<<1, 192>>>(w_indiv, w_social, tp_w, tp_b, tpr_w, tpr_b,
                   tpi_w, tpi_b, tpir_w, tpir_b);
    kB<<<128, 256, 80 * 1024>>>();
    kC<<<512, 160>>>(obs_vel, noise, w_noise,
                     sp_w, sp_b, spr_w, spr_b,
                     spi_w, spi_b, spir_w, spir_b, out);
}

// round 3
// speedup vs baseline: 1.6106x; 1.3519x over previous
#include <cuda_runtime.h>
#include <cstdint>

#define NN 4096
#define TT 8
#define KTOP 4
#define RR 8
#define DKK 64
#define BB 20

typedef unsigned long long ull;

__device__ __align__(16) float g_q[NN * DKK];
__device__ __align__(16) float g_k[NN * DKK];
__device__ __align__(16) float g_rq[NN * DKK];
__device__ __align__(16) float g_C[RR * 24 * 36];
__device__ __align__(16) float g_pv[NN * 8];
__device__ __align__(16) int g_pi[NN * 8];
__device__ int g_ctx[NN * KTOP];
__device__ int g_rule[NN];

__device__ __forceinline__ ull pack2(float a, float b) {
    ull r;
    asm("mov.b64 %0, {%1, %2};" : "=l"(r) : "f"(a), "f"(b));
    return r;
}
__device__ __forceinline__ void unpack2(ull v, float& a, float& b) {
    asm("mov.b64 {%0, %1}, %2;" : "=f"(a), "=f"(b) : "l"(v));
}
__device__ __forceinline__ ull fma2(ull a, ull b, ull c) {
    ull d;
    asm("fma.rn.f32x2 %0, %1, %2, %3;" : "=l"(d) : "l"(a), "l"(b), "l"(c));
    return d;
}

// top-4 insert: value desc, ties -> lower index (matches lax.top_k)
__device__ __forceinline__ void ins4(float v, int idx, float* tv, int* ti) {
    if (v > tv[3] || (v == tv[3] && idx < ti[3])) {
        tv[3] = v; ti[3] = idx;
#pragma unroll
        for (int j = 3; j > 0; j--) {
            bool sw = (tv[j] > tv[j - 1]) || (tv[j] == tv[j - 1] && ti[j] < ti[j - 1]);
            if (sw) {
                float f = tv[j]; tv[j] = tv[j - 1]; tv[j - 1] = f;
                int q = ti[j]; ti[j] = ti[j - 1]; ti[j - 1] = q;
            }
        }
    }
}

// ---------------------------------------------------------------------------
// kA: x[4096x32] @ W[32x192] -> g_q | g_k | g_rq  (rule proj zero-padded)
// ---------------------------------------------------------------------------
__global__ __launch_bounds__(256) void kA(
    const float* __restrict__ obs, const float* __restrict__ obs_vel,
    const float* __restrict__ wq_rule, const float* __restrict__ bq_rule,
    const float* __restrict__ wq_ctx, const float* __restrict__ bq_ctx,
    const float* __restrict__ wk_ctx, const float* __restrict__ bk_ctx)
{
    __shared__ __align__(16) ull x2_s[32 * 64];  // [i][node], dup pairs
    __shared__ __align__(16) ull w_s[32 * 96];   // [i][colpair]
    int tid = threadIdx.x;
    int n0 = blockIdx.x * 64;

    float* xf = (float*)x2_s;
    for (int e = tid; e < 32 * 64; e += 256) {
        int i = e >> 6, node = e & 63;
        int t = i >> 2, c = i & 3;
        const float* src = (c < 2) ? obs : obs_vel;
        float v = src[(c & 1) * NN * TT + (n0 + node) * TT + t];
        xf[e * 2] = v; xf[e * 2 + 1] = v;
    }
    float* wf = (float*)w_s;
    for (int e = tid; e < 32 * 192; e += 256) {
        int i = e / 192, col = e % 192;
        float v;
        if (col < 64) v = wq_ctx[i * 64 + col];
        else if (col < 128) v = wk_ctx[i * 64 + col - 64];
        else {
            int c = i & 3;
            if (c >= 2) v = wq_rule[((i >> 2) * 2 + (c - 2)) * 64 + (col - 128)];
            else v = 0.f;
        }
        wf[i * 192 + col] = v;
    }
    __syncthreads();

    int w = tid >> 5, tx = tid & 31;
    int rbase = w * 8;
    ull bp[3];
#pragma unroll
    for (int j = 0; j < 3; j++) {
        int c2 = (tx * 3 + j) * 2;
        float b0, b1;
        if (c2 < 64) { b0 = bq_ctx[c2]; b1 = bq_ctx[c2 + 1]; }
        else if (c2 < 128) { b0 = bk_ctx[c2 - 64]; b1 = bk_ctx[c2 - 63]; }
        else { b0 = bq_rule[c2 - 128]; b1 = bq_rule[c2 - 127]; }
        bp[j] = pack2(b0, b1);
    }
    ull acc[8][3];
#pragma unroll
    for (int r = 0; r < 8; r++)
#pragma unroll
        for (int j = 0; j < 3; j++) acc[r][j] = bp[j];

#pragma unroll 8
    for (int kk = 0; kk < 32; kk++) {
        const ulonglong2* qp = (const ulonglong2*)(x2_s + kk * 64 + rbase);
        ulonglong2 q0 = qp[0], q1 = qp[1], q2v = qp[2], q3 = qp[3];
        ull qr[8] = { q0.x, q0.y, q1.x, q1.y, q2v.x, q2v.y, q3.x, q3.y };
        ull wv0 = w_s[kk * 96 + tx * 3 + 0];
        ull wv1 = w_s[kk * 96 + tx * 3 + 1];
        ull wv2 = w_s[kk * 96 + tx * 3 + 2];
#pragma unroll
        for (int r = 0; r < 8; r++) {
            acc[r][0] = fma2(qr[r], wv0, acc[r][0]);
            acc[r][1] = fma2(qr[r], wv1, acc[r][1]);
            acc[r][2] = fma2(qr[r], wv2, acc[r][2]);
        }
    }
#pragma unroll
    for (int r = 0; r < 8; r++) {
        int node = n0 + rbase + r;
#pragma unroll
        for (int j = 0; j < 3; j++) {
            int c2 = (tx * 3 + j) * 2;
            float v0, v1;
            unpack2(acc[r][j], v0, v1);
            float* dst = (c2 < 64) ? g_q : (c2 < 128) ? g_k : g_rq;
            int cc = c2 & 63;
            dst[node * 64 + cc] = v0;
            dst[node * 64 + cc + 1] = v1;
        }
    }
}

// ---------------------------------------------------------------------------
// kR: rule argmax from g_rq @ rule_emb^T
// ---------------------------------------------------------------------------
__global__ __launch_bounds__(128) void kR(const float* __restrict__ rule_emb)
{
    __shared__ float s_emb[64 * 8];
    int tid = threadIdx.x;
    for (int e = tid; e < 512; e += 128) s_emb[e] = rule_emb[(e & 7) * 64 + (e >> 3)];
    __syncthreads();
    int n = blockIdx.x * 128 + tid;
    float lg[8];
#pragma unroll
    for (int r = 0; r < 8; r++) lg[r] = 0.f;
#pragma unroll
    for (int og = 0; og < 16; og++) {
        float4 v = *(const float4*)&g_rq[n * 64 + og * 4];
        float vv[4] = { v.x, v.y, v.z, v.w };
#pragma unroll
        for (int e = 0; e < 4; e++) {
            int o = og * 4 + e;
#pragma unroll
            for (int r = 0; r < 8; r++) lg[r] = fmaf(vv[e], s_emb[o * 8 + r], lg[r]);
        }
    }
    int best = 0;
    float bv = lg[0];
#pragma unroll
    for (int r = 1; r < 8; r++)
        if (lg[r] > bv) { bv = lg[r]; best = r; }
    g_rule[n] = best;
}

// ---------------------------------------------------------------------------
// kB: scores = q @ k^T + per-row top-4 over a 2048-col half.
// grid (128, 2) x 256 thr. Block: 32 rows x 2048 cols, 8 tiles of 256.
// Warp = 4 rows x 256 cols; thread = 4 rows x 8 cols (two float4 groups).
// smem: k float[64][256] (64KB) + q dup ull[64][32] (16KB) = 80KB.
// ---------------------------------------------------------------------------
__global__ __launch_bounds__(256, 2) void kB()
{
    extern __shared__ __align__(16) ull dsm[];
    float* k_s = (float*)dsm;        // [kk][col] 64x256
    ull* q2 = dsm + 8192;            // [kk][row] dup, 64x32
    int tid = threadIdx.x;
    int w = tid >> 5, tx = tid & 31;
    int row0 = blockIdx.x * 32;
    int half = blockIdx.y;
    int colbase = half * 2048;
    int r0 = w * 4;

    // stage q2 (dup pairs): thread -> (row = tid&31, kk block of 8)
    {
        int row = tid & 31, kkb = (tid >> 5) * 8;
        const float4* src = (const float4*)&g_q[(row0 + row) * 64 + kkb];
        float4 a = src[0], b = src[1];
        float vv[8] = { a.x, a.y, a.z, a.w, b.x, b.y, b.z, b.w };
#pragma unroll
        for (int e = 0; e < 8; e++) q2[(kkb + e) * 32 + row] = pack2(vv[e], vv[e]);
    }

    float tv[4][4];
    int ti[4][4];
#pragma unroll
    for (int r = 0; r < 4; r++)
#pragma unroll
        for (int j = 0; j < 4; j++) { tv[r][j] = -3.4e38f; ti[r][j] = 0x7fffffff; }

    for (int ct = 0; ct < 8; ct++) {
        int c0 = colbase + ct * 256;
        __syncthreads();
        // stage k tile: thread handles node c0+tid, all 64 kk (conflict-free STS)
        {
            const float4* src = (const float4*)&g_k[(size_t)(c0 + tid) * 64];
#pragma unroll
            for (int j = 0; j < 16; j++) {
                float4 v = src[j];
                k_s[(j * 4 + 0) * 256 + tid] = v.x;
                k_s[(j * 4 + 1) * 256 + tid] = v.y;
                k_s[(j * 4 + 2) * 256 + tid] = v.z;
                k_s[(j * 4 + 3) * 256 + tid] = v.w;
            }
        }
        __syncthreads();

        ull acc[4][4];
#pragma unroll
        for (int r = 0; r < 4; r++)
#pragma unroll
            for (int j = 0; j < 4; j++) acc[r][j] = 0ull;

#pragma unroll 8
        for (int kk = 0; kk < 64; kk++) {
            ulonglong2 qa = *(const ulonglong2*)(q2 + kk * 32 + r0);      // uniform -> broadcast
            ulonglong2 qb = *(const ulonglong2*)(q2 + kk * 32 + r0 + 2);
            ull qr[4] = { qa.x, qa.y, qb.x, qb.y };
            ulonglong2 ka = *(const ulonglong2*)(k_s + kk * 256 + tx * 4);        // cols A
            ulonglong2 kb = *(const ulonglong2*)(k_s + kk * 256 + 128 + tx * 4);  // cols B
#pragma unroll
            for (int r = 0; r < 4; r++) {
                acc[r][0] = fma2(qr[r], ka.x, acc[r][0]);
                acc[r][1] = fma2(qr[r], ka.y, acc[r][1]);
                acc[r][2] = fma2(qr[r], kb.x, acc[r][2]);
                acc[r][3] = fma2(qr[r], kb.y, acc[r][3]);
            }
        }
#pragma unroll
        for (int r = 0; r < 4; r++)
#pragma unroll
            for (int j = 0; j < 4; j++) {
                float v0, v1;
                unpack2(acc[r][j], v0, v1);
                int col = (j < 2) ? (c0 + tx * 4 + j * 2) : (c0 + 128 + tx * 4 + (j - 2) * 2);
                ins4(v0, col, tv[r], ti[r]);
                ins4(v1, col + 1, tv[r], ti[r]);
            }
    }
    // block merge via smem overlay (32 rows x 32 threads x 4 entries)
    __syncthreads();
    float* scv = (float*)dsm;
    int* sci = (int*)(scv + 4096);
#pragma unroll
    for (int r = 0; r < 4; r++)
#pragma unroll
        for (int j = 0; j < 4; j++) {
            int e = ((r0 + r) * 32 + tx) * 4 + j;
            scv[e] = tv[r][j];
            sci[e] = ti[r][j];
        }
    __syncthreads();
    if (tid < 32) {
        float bvv[4]; int bii[4];
#pragma unroll
        for (int j = 0; j < 4; j++) { bvv[j] = -3.4e38f; bii[j] = 0x7fffffff; }
        int base = tid * 128;
        for (int p = 0; p < 128; p++) ins4(scv[base + p], sci[base + p], bvv, bii);
        int row = row0 + tid;
#pragma unroll
        for (int j = 0; j < 4; j++) {
            g_pv[row * 8 + half * 4 + j] = bvv[j];
            g_pi[row * 8 + half * 4 + j] = bii[j];
        }
    }
}

// ---------------------------------------------------------------------------
// kM: merge the two column-half partial top-4s per row
// ---------------------------------------------------------------------------
__global__ __launch_bounds__(256) void kM()
{
    int n = blockIdx.x * 256 + threadIdx.x;
    float bv[4]; int bi[4];
#pragma unroll
    for (int j = 0; j < 4; j++) { bv[j] = -3.4e38f; bi[j] = 0x7fffffff; }
#pragma unroll
    for (int p = 0; p < 8; p++) ins4(g_pv[n * 8 + p], g_pi[n * 8 + p], bv, bi);
#pragma unroll
    for (int j = 0; j < 4; j++) g_ctx[n * 4 + j] = bi[j];
}

// ---------------------------------------------------------------------------
// kP: precompute rule-combined time-conv matrices C[r][24][36]
// ---------------------------------------------------------------------------
__global__ void kP(
    const float* __restrict__ w_indiv, const float* __restrict__ w_social,
    const float* __restrict__ tp_w, const float* __restrict__ tp_b,
    const float* __restrict__ tpr_w, const float* __restrict__ tpr_b,
    const float* __restrict__ tpi_w, const float* __restrict__ tpi_b,
    const float* __restrict__ tpir_w, const float* __restrict__ tpir_b)
{
    int t = threadIdx.x;
    if (t >= 192) return;
    int r = t / 24, o2 = t % 24, o = o2 >> 1, pos = o2 & 1;
    float wi = w_indiv[r], ws = w_social[r];
    float* dst = g_C + (r * 24 + o2) * 36;
#pragma unroll
    for (int c = 0; c < 8; c++) {
        int wb = (r * 12 + o) * 8 + c;
        const float* wt = tpi_w + wb * 3;
        float wri = tpir_w[wb];
        float ci0 = pos == 0 ? (wt[1] + wri) : wt[0];
        float ci1 = pos == 0 ? wt[2] : (wt[1] + wri);
        dst[c] = wi * ci0;
        dst[8 + c] = wi * ci1;
        const float* ut = tp_w + wb * 3;
        float urs = tpr_w[wb];
        float cs0 = pos == 0 ? (ut[1] + urs) : ut[0];
        float cs1 = pos == 0 ? ut[2] : (ut[1] + urs);
        dst[16 + c] = ws * cs0;
        dst[24 + c] = ws * cs1;
    }
    dst[32] = wi * (tpi_b[r * 12 + o] + tpir_b[r * 12 + o])
            + ws * (tp_b[r * 12 + o] + tpr_b[r * 12 + o]);
    dst[33] = 0.f; dst[34] = 0.f; dst[35] = 0.f;
}

// ---------------------------------------------------------------------------
// kC: gather + selected-rule spatial convs + combined matvec. 8 nodes x 20 b.
// ---------------------------------------------------------------------------
__global__ __launch_bounds__(160) void kC(
    const float* __restrict__ obs_vel, const float* __restrict__ noise,
    const float* __restrict__ w_noise,
    const float* __restrict__ sp_w, const float* __restrict__ sp_b,
    const float* __restrict__ spr_w, const float* __restrict__ spr_b,
    const float* __restrict__ spi_w, const float* __restrict__ spi_b,
    const float* __restrict__ spir_w, const float* __restrict__ spir_b,
    float* __restrict__ out)
{
    __shared__ __align__(16) float s_C[8 * 24 * 36];
    __shared__ float s_sp_w[480], s_sp_b[16], s_spr_w[160], s_spr_b[16];
    __shared__ float s_spi_w[96], s_spi_b[16], s_spir_w[32], s_spir_b[16];
    __shared__ float s_wn[8], s_noise[BB * 2];
    __shared__ float s_ov[128], s_cvx[512];
    __shared__ int s_rule[8];

    int tid = threadIdx.x;
    int n0 = blockIdx.x * 8;

    for (int i = tid; i < 8 * 24 * 36; i += 160) s_C[i] = g_C[i];
    for (int i = tid; i < 480; i += 160) s_sp_w[i] = sp_w[i];
    for (int i = tid; i < 160; i += 160) s_spr_w[i] = spr_w[i];
    if (tid < 96) s_spi_w[tid] = spi_w[tid];
    if (tid < 32) s_spir_w[tid] = spir_w[tid];
    if (tid < 16) {
        s_sp_b[tid] = sp_b[tid]; s_spr_b[tid] = spr_b[tid];
        s_spi_b[tid] = spi_b[tid]; s_spir_b[tid] = spir_b[tid];
    }
    if (tid < 8) { s_wn[tid] = w_noise[tid]; s_rule[tid] = g_rule[n0 + tid]; }
    if (tid < 40) s_noise[tid] = noise[tid];
    for (int i = tid; i < 128; i += 160) {
        int node = i >> 4, s = (i >> 3) & 1, t = i & 7;
        s_ov[i] = obs_vel[s * NN * TT + (n0 + node) * TT + t];
    }
    for (int i = tid; i < 512; i += 160) {
        int node = i >> 6, rem = i & 63, k = rem >> 4, s = (rem >> 3) & 1, t = rem & 7;
        int nb = g_ctx[(n0 + node) * 4 + k];
        s_cvx[i] = obs_vel[s * NN * TT + nb * TT + t];
    }
    __syncthreads();

    int node = tid / 20, b = tid - node * 20;
    int n = n0 + node;
    int r = s_rule[node];
    float wn = s_wn[r];
    float nz0 = s_noise[b * 2 + 0] * wn;
    float nz1 = s_noise[b * 2 + 1] * wn;

    float v0[8], v1[8];
#pragma unroll
    for (int t = 0; t < 8; t++) {
        v0[t] = s_ov[node * 16 + t] + nz0;
        v1[t] = s_ov[node * 16 + 8 + t] + nz1;
    }

    float vals[32];

    {
        const float* pw3 = s_spi_w + r * 12;
        const float* pw1 = s_spir_w + r * 4;
#pragma unroll
        for (int so = 0; so < 2; so++) {
            float b3 = s_spi_b[r * 2 + so], b1 = s_spir_b[r * 2 + so];
            float w00 = pw3[so * 6 + 0], w01 = pw3[so * 6 + 1], w02 = pw3[so * 6 + 2];
            float w10 = pw3[so * 6 + 3], w11 = pw3[so * 6 + 4], w12 = pw3[so * 6 + 5];
            float wr0 = pw1[so * 2 + 0], wr1 = pw1[so * 2 + 1];
#pragma unroll
            for (int t = 0; t < 8; t++) {
                float a = b3;
                a = fmaf(w01, v0[t], a);
                a = fmaf(w11, v1[t], a);
                if (t > 0) { a = fmaf(w00, v0[t - 1], a); a = fmaf(w10, v1[t - 1], a); }
                if (t < 7) { a = fmaf(w02, v0[t + 1], a); a = fmaf(w12, v1[t + 1], a); }
                a = fmaxf(a, 0.f);
                float c1 = b1;
                c1 = fmaf(wr0, v0[t], c1);
                c1 = fmaf(wr1, v1[t], c1);
                vals[so * 8 + t] = a + c1;
            }
        }
    }

    {
        float a0[8], a1[8], c0[8], c1[8];
        float ba0 = s_sp_b[r * 2], ba1 = s_sp_b[r * 2 + 1];
        float bc0 = s_spr_b[r * 2], bc1 = s_spr_b[r * 2 + 1];
#pragma unroll
        for (int t = 0; t < 8; t++) { a0[t] = ba0; a1[t] = ba1; c0[t] = bc0; c1[t] = bc1; }
        const float* q3 = s_sp_w + r * 60;
        const float* q1 = s_spr_w + r * 20;

#define PROC_CH(ci, VV)                                                        \
        {                                                                      \
            float u0 = q3[(ci) * 3], u1 = q3[(ci) * 3 + 1], u2 = q3[(ci) * 3 + 2]; \
            float z0 = q3[30 + (ci) * 3], z1 = q3[30 + (ci) * 3 + 1], z2 = q3[30 + (ci) * 3 + 2]; \
            float ur = q1[(ci)], zr = q1[10 + (ci)];                           \
            _Pragma("unroll")                                                  \
            for (int t = 0; t < 8; t++) {                                      \
                float x = VV[t];                                               \
                a0[t] = fmaf(u1, x, a0[t]); a1[t] = fmaf(z1, x, a1[t]);        \
                c0[t] = fmaf(ur, x, c0[t]); c1[t] = fmaf(zr, x, c1[t]);        \
                if (t > 0) { a0[t] = fmaf(u0, VV[t - 1], a0[t]); a1[t] = fmaf(z0, VV[t - 1], a1[t]); } \
                if (t < 7) { a0[t] = fmaf(u2, VV[t + 1], a0[t]); a1[t] = fmaf(z2, VV[t + 1], a1[t]); } \
            }                                                                  \
        }

        PROC_CH(0, v0)
        PROC_CH(1, v1)
#pragma unroll
        for (int k = 0; k < 4; k++) {
            float nb0[8], nb1[8];
#pragma unroll
            for (int t = 0; t < 8; t++) {
                nb0[t] = s_cvx[node * 64 + k * 16 + t] + nz0;
                nb1[t] = s_cvx[node * 64 + k * 16 + 8 + t] + nz1;
            }
            PROC_CH(2 + k * 2 + 0, nb0)
            PROC_CH(2 + k * 2 + 1, nb1)
        }
#undef PROC_CH
#pragma unroll
        for (int t = 0; t < 8; t++) {
            vals[16 + t] = fmaxf(a0[t], 0.f) + c0[t];
            vals[24 + t] = fmaxf(a1[t], 0.f) + c1[t];
        }
    }

    ull pk[16];
#pragma unroll
    for (int p = 0; p < 16; p++) pk[p] = pack2(vals[2 * p], vals[2 * p + 1]);

    const float* Cb = s_C + r * 24 * 36;
    float* outp = out + ((size_t)b * NN + n) * 24;
#pragma unroll 4
    for (int o2 = 0; o2 < 24; o2++) {
        const ulonglong2* cp = (const ulonglong2*)(Cb + o2 * 36);
        ull acc = pack2(Cb[o2 * 36 + 32], 0.f);
#pragma unroll
        for (int p = 0; p < 8; p++) {
            ulonglong2 cc = cp[p];
            acc = fma2(cc.x, pk[2 * p], acc);
            acc = fma2(cc.y, pk[2 * p + 1], acc);
        }
        float lo, hi;
        unpack2(acc, lo, hi);
        outp[o2] = lo + hi;
    }
}

// ---------------------------------------------------------------------------
extern "C" void kernel_launch(void* const* d_in, const int* in_sizes, int n_in,
                              void* d_out, int out_size)
{
    const float* obs      = (const float*)d_in[0];
    const float* obs_vel  = (const float*)d_in[1];
    const float* noise    = (const float*)d_in[2];
    const float* wq_rule  = (const float*)d_in[3];
    const float* bq_rule  = (const float*)d_in[4];
    const float* wq_ctx   = (const float*)d_in[5];
    const float* bq_ctx   = (const float*)d_in[6];
    const float* wk_ctx   = (const float*)d_in[7];
    const float* bk_ctx   = (const float*)d_in[8];
    const float* rule_emb = (const float*)d_in[9];
    const float* w_noise  = (const float*)d_in[10];
    const float* w_indiv  = (const float*)d_in[11];
    const float* w_social = (const float*)d_in[12];
    const float* sp_w  = (const float*)d_in[13];
    const float* sp_b  = (const float*)d_in[14];
    const float* spr_w = (const float*)d_in[15];
    const float* spr_b = (const float*)d_in[16];
    const float* tp_w  = (const float*)d_in[17];
    const float* tp_b  = (const float*)d_in[18];
    const float* tpr_w = (const float*)d_in[19];
    const float* tpr_b = (const float*)d_in[20];
    const float* spi_w  = (const float*)d_in[21];
    const float* spi_b  = (const float*)d_in[22];
    const float* spir_w = (const float*)d_in[23];
    const float* spir_b = (const float*)d_in[24];
    const float* tpi_w  = (const float*)d_in[25];
    const float* tpi_b  = (const float*)d_in[26];
    const float* tpir_w = (const float*)d_in[27];
    const float* tpir_b = (const float*)d_in[28];
    float* out = (float*)d_out;

    static bool attr_set = false;
    if (!attr_set) {
        cudaFuncSetAttribute(kB, cudaFuncAttributeMaxDynamicSharedMemorySize, 80 * 1024);
        attr_set = true;
    }

    kA<<<64, 256>>>(obs, obs_vel, wq_rule, bq_rule, wq_ctx, bq_ctx, wk_ctx, bk_ctx);
    kR<<<32, 128>>>(rule_emb);
    kP<<<1, 192>>>(w_indiv, w_social, tp_w, tp_b, tpr_w, tpr_b,
                   tpi_w, tpi_b, tpir_w, tpir_b);
    kB<<<dim3(128, 2), 256, 80 * 1024>>>();
    kM<<<16, 256>>>();
    kC<<<512, 160>>>(obs_vel, noise, w_noise,
                     sp_w, sp_b, spr_w, spr_b,
                     spi_w, spi_b, spir_w, spir_b, out);
}

// round 5
// speedup vs baseline: 1.7000x; 1.0555x over previous
#include <cuda_runtime.h>
#include <cuda_bf16.h>
#include <cstdint>

#define NN 4096
#define TT 8
#define KTOP 4
#define RR 8
#define DKK 64
#define BB 20

typedef unsigned long long ull;

__device__ __align__(16) float g_q[NN * DKK];
__device__ __align__(16) float g_k[NN * DKK];
__device__ __align__(16) float g_rq[NN * DKK];
__device__ __align__(16) __nv_bfloat16 g_qh[NN * DKK];
__device__ __align__(16) __nv_bfloat16 g_kh[NN * DKK];
__device__ __align__(16) float g_C[RR * 24 * 36];
__device__ __align__(16) float g_pv[NN * 8];
__device__ __align__(16) int g_pi[NN * 8];
__device__ __align__(16) int g_cand[NN * 64];
__device__ int g_ctx[NN * KTOP];
__device__ int g_rule[NN];

// ---------------- small helpers ----------------
__device__ __forceinline__ ull pack2(float a, float b) {
    ull r;
    asm("mov.b64 %0, {%1, %2};" : "=l"(r) : "f"(a), "f"(b));
    return r;
}
__device__ __forceinline__ void unpack2(ull v, float& a, float& b) {
    asm("mov.b64 {%0, %1}, %2;" : "=f"(a), "=f"(b) : "l"(v));
}
__device__ __forceinline__ ull fma2(ull a, ull b, ull c) {
    ull d;
    asm("fma.rn.f32x2 %0, %1, %2, %3;" : "=l"(d) : "l"(a), "l"(b), "l"(c));
    return d;
}
__device__ __forceinline__ void ins4(float v, int idx, float* tv, int* ti) {
    if (v > tv[3] || (v == tv[3] && idx < ti[3])) {
        tv[3] = v; ti[3] = idx;
#pragma unroll
        for (int j = 3; j > 0; j--) {
            bool sw = (tv[j] > tv[j - 1]) || (tv[j] == tv[j - 1] && ti[j] < ti[j - 1]);
            if (sw) {
                float f = tv[j]; tv[j] = tv[j - 1]; tv[j - 1] = f;
                int q = ti[j]; ti[j] = ti[j - 1]; ti[j - 1] = q;
            }
        }
    }
}
__device__ __forceinline__ uint32_t smem_to_u32(const void* p) {
    uint32_t a;
    asm("{ .reg .u64 t; cvta.to.shared.u64 t, %1; cvt.u32.u64 %0, t; }" : "=r"(a) : "l"(p));
    return a;
}
// XOR swizzle: rows of 128B, 16B chunks permuted by row
#define SWZ(row, byteoff) \
    ((row) * 128 + (((((byteoff) >> 4) ^ ((row) & 7)) << 4)) + ((byteoff) & 15))

// ---------------------------------------------------------------------------
// kA: x[4096x32] @ W[32x192] -> g_q | g_k | g_rq, plus bf16 copies of q,k
// ---------------------------------------------------------------------------
__global__ __launch_bounds__(256) void kA(
    const float* __restrict__ obs, const float* __restrict__ obs_vel,
    const float* __restrict__ wq_rule, const float* __restrict__ bq_rule,
    const float* __restrict__ wq_ctx, const float* __restrict__ bq_ctx,
    const float* __restrict__ wk_ctx, const float* __restrict__ bk_ctx)
{
    __shared__ __align__(16) ull x2_s[32 * 64];
    __shared__ __align__(16) ull w_s[32 * 96];
    int tid = threadIdx.x;
    int n0 = blockIdx.x * 64;

    float* xf = (float*)x2_s;
    for (int e = tid; e < 32 * 64; e += 256) {
        int i = e >> 6, node = e & 63;
        int t = i >> 2, c = i & 3;
        const float* src = (c < 2) ? obs : obs_vel;
        float v = src[(c & 1) * NN * TT + (n0 + node) * TT + t];
        xf[e * 2] = v; xf[e * 2 + 1] = v;
    }
    float* wf = (float*)w_s;
    for (int e = tid; e < 32 * 192; e += 256) {
        int i = e / 192, col = e % 192;
        float v;
        if (col < 64) v = wq_ctx[i * 64 + col];
        else if (col < 128) v = wk_ctx[i * 64 + col - 64];
        else {
            int c = i & 3;
            if (c >= 2) v = wq_rule[((i >> 2) * 2 + (c - 2)) * 64 + (col - 128)];
            else v = 0.f;
        }
        wf[i * 192 + col] = v;
    }
    __syncthreads();

    int w = tid >> 5, tx = tid & 31;
    int rbase = w * 8;
    ull bp[3];
#pragma unroll
    for (int j = 0; j < 3; j++) {
        int c2 = (tx * 3 + j) * 2;
        float b0, b1;
        if (c2 < 64) { b0 = bq_ctx[c2]; b1 = bq_ctx[c2 + 1]; }
        else if (c2 < 128) { b0 = bk_ctx[c2 - 64]; b1 = bk_ctx[c2 - 63]; }
        else { b0 = bq_rule[c2 - 128]; b1 = bq_rule[c2 - 127]; }
        bp[j] = pack2(b0, b1);
    }
    ull acc[8][3];
#pragma unroll
    for (int r = 0; r < 8; r++)
#pragma unroll
        for (int j = 0; j < 3; j++) acc[r][j] = bp[j];

#pragma unroll 8
    for (int kk = 0; kk < 32; kk++) {
        const ulonglong2* qp = (const ulonglong2*)(x2_s + kk * 64 + rbase);
        ulonglong2 q0 = qp[0], q1 = qp[1], q2v = qp[2], q3 = qp[3];
        ull qr[8] = { q0.x, q0.y, q1.x, q1.y, q2v.x, q2v.y, q3.x, q3.y };
        ull wv0 = w_s[kk * 96 + tx * 3 + 0];
        ull wv1 = w_s[kk * 96 + tx * 3 + 1];
        ull wv2 = w_s[kk * 96 + tx * 3 + 2];
#pragma unroll
        for (int r = 0; r < 8; r++) {
            acc[r][0] = fma2(qr[r], wv0, acc[r][0]);
            acc[r][1] = fma2(qr[r], wv1, acc[r][1]);
            acc[r][2] = fma2(qr[r], wv2, acc[r][2]);
        }
    }
#pragma unroll
    for (int r = 0; r < 8; r++) {
        int node = n0 + rbase + r;
#pragma unroll
        for (int j = 0; j < 3; j++) {
            int c2 = (tx * 3 + j) * 2;
            float v0, v1;
            unpack2(acc[r][j], v0, v1);
            int cc = c2 & 63;
            if (c2 < 64) {
                g_q[node * 64 + cc] = v0;
                g_q[node * 64 + cc + 1] = v1;
                *(__nv_bfloat162*)&g_qh[node * 64 + cc] = __floats2bfloat162_rn(v0, v1);
            } else if (c2 < 128) {
                g_k[node * 64 + cc] = v0;
                g_k[node * 64 + cc + 1] = v1;
                *(__nv_bfloat162*)&g_kh[node * 64 + cc] = __floats2bfloat162_rn(v0, v1);
            } else {
                g_rq[node * 64 + cc] = v0;
                g_rq[node * 64 + cc + 1] = v1;
            }
        }
    }
}

// ---------------------------------------------------------------------------
// kR: rule argmax from g_rq @ rule_emb^T
// ---------------------------------------------------------------------------
__global__ __launch_bounds__(128) void kR(const float* __restrict__ rule_emb)
{
    __shared__ float s_emb[64 * 8];
    int tid = threadIdx.x;
    for (int e = tid; e < 512; e += 128) s_emb[e] = rule_emb[(e & 7) * 64 + (e >> 3)];
    __syncthreads();
    int n = blockIdx.x * 128 + tid;
    float lg[8];
#pragma unroll
    for (int r = 0; r < 8; r++) lg[r] = 0.f;
#pragma unroll
    for (int og = 0; og < 16; og++) {
        float4 v = *(const float4*)&g_rq[n * 64 + og * 4];
        float vv[4] = { v.x, v.y, v.z, v.w };
#pragma unroll
        for (int e = 0; e < 4; e++) {
            int o = og * 4 + e;
#pragma unroll
            for (int r = 0; r < 8; r++) lg[r] = fmaf(vv[e], s_emb[o * 8 + r], lg[r]);
        }
    }
    int best = 0;
    float bv = lg[0];
#pragma unroll
    for (int r = 1; r < 8; r++)
        if (lg[r] > bv) { bv = lg[r]; best = r; }
    g_rule[n] = best;
}

// ---------------------------------------------------------------------------
// kB_hmma: scores via mma.sync bf16 HMMA + per-thread top-4 candidates.
// grid (64 rowblocks, 2 colsplits) x 256 thr, 2 CTAs/SM.
// CTA: 64 rows x 2048 cols, K=64. Warp = 16 rows x 128 cols per 256-col tile.
// smem: A 8KB + B 2x32KB (double-buffered via cp.async) = 72KB dynamic.
// Candidates: 8 threads/row x top-4 = 32 per row per split -> g_cand.
// ---------------------------------------------------------------------------
__global__ __launch_bounds__(256, 2) void kB_hmma()
{
    extern __shared__ char smem[];
    char* As = smem;               // 64 x 128B
    char* Bs0 = smem + 8192;       // 256 x 128B
    char* Bs1 = smem + 8192 + 32768;
    int tid = threadIdx.x, lane = tid & 31, wid = tid >> 5;
    int row0 = blockIdx.x * 64;
    int split = blockIdx.y;
    int colbase = split * 2048;

    // stage A (swizzled)
    for (int e = tid; e < 512; e += 256) {
        int r = e >> 3, c = e & 7;
        uint4 v = *(const uint4*)((const char*)g_qh + (size_t)(row0 + r) * 128 + c * 16);
        *(uint4*)(As + r * 128 + ((c ^ (r & 7)) << 4)) = v;
    }
    // prefetch B tile 0
    {
        int r = tid;
        const char* src = (const char*)g_kh + (size_t)(colbase + r) * 128;
        char* dst = Bs0 + r * 128;
#pragma unroll
        for (int c = 0; c < 8; c++) {
            uint32_t daddr = smem_to_u32(dst + ((c ^ (r & 7)) << 4));
            asm volatile("cp.async.cg.shared.global [%0], [%1], 16;"
                         :: "r"(daddr), "l"(src + c * 16));
        }
        asm volatile("cp.async.commit_group;");
    }
    __syncthreads();

    int rg = wid >> 1, ch = wid & 1;
    int m0 = rg * 16;

    // A fragments: a[k][0..3] for 4 k-steps of 16
    uint32_t a[4][4];
    {
        int arow = m0 + (lane & 15);
        int kbh = ((lane >> 4) & 1) * 16;
#pragma unroll
        for (int k = 0; k < 4; k++) {
            int byteoff = k * 32 + kbh;
            uint32_t addr = smem_to_u32(As + SWZ(arow, byteoff));
            asm volatile("ldmatrix.sync.aligned.m8n8.x4.shared.b16 {%0,%1,%2,%3}, [%4];"
                : "=r"(a[k][0]), "=r"(a[k][1]), "=r"(a[k][2]), "=r"(a[k][3]) : "r"(addr));
        }
    }

    int brow_off = (lane & 7) + ((lane & 16) >> 1);
    int bkb = (lane & 8) ? 16 : 0;

    float tv[2][4];
    int ti[2][4];
#pragma unroll
    for (int h = 0; h < 2; h++)
#pragma unroll
        for (int j = 0; j < 4; j++) { tv[h][j] = -3.4e38f; ti[h][j] = 0x7fffffff; }

    for (int t = 0; t < 8; t++) {
        if (t < 7) {
            char* dst0 = ((t + 1) & 1) ? Bs1 : Bs0;
            int r = tid;
            const char* src = (const char*)g_kh + (size_t)(colbase + (t + 1) * 256 + r) * 128;
            char* dst = dst0 + r * 128;
#pragma unroll
            for (int c = 0; c < 8; c++) {
                uint32_t daddr = smem_to_u32(dst + ((c ^ (r & 7)) << 4));
                asm volatile("cp.async.cg.shared.global [%0], [%1], 16;"
                             :: "r"(daddr), "l"(src + c * 16));
            }
            asm volatile("cp.async.commit_group;");
            asm volatile("cp.async.wait_group 1;");
        } else {
            asm volatile("cp.async.wait_group 0;");
        }
        __syncthreads();

        const char* B = (t & 1) ? Bs1 : Bs0;
        int coltile = colbase + t * 256;
#pragma unroll 2
        for (int np = 0; np < 8; np++) {
            int n0 = ch * 128 + np * 16;
            uint32_t b[4][4];
#pragma unroll
            for (int k = 0; k < 4; k++) {
                int brow = n0 + brow_off;
                int byteoff = k * 32 + bkb;
                uint32_t addr = smem_to_u32(B + SWZ(brow, byteoff));
                asm volatile("ldmatrix.sync.aligned.m8n8.x4.shared.b16 {%0,%1,%2,%3}, [%4];"
                    : "=r"(b[k][0]), "=r"(b[k][1]), "=r"(b[k][2]), "=r"(b[k][3]) : "r"(addr));
            }
            float c0[4] = {0.f, 0.f, 0.f, 0.f};
            float c1[4] = {0.f, 0.f, 0.f, 0.f};
#pragma unroll
            for (int k = 0; k < 4; k++) {
                asm volatile(
                    "mma.sync.aligned.m16n8k16.row.col.f32.bf16.bf16.f32 "
                    "{%0,%1,%2,%3}, {%4,%5,%6,%7}, {%8,%9}, {%0,%1,%2,%3};"
                    : "+f"(c0[0]), "+f"(c0[1]), "+f"(c0[2]), "+f"(c0[3])
                    : "r"(a[k][0]), "r"(a[k][1]), "r"(a[k][2]), "r"(a[k][3]),
                      "r"(b[k][0]), "r"(b[k][1]));
                asm volatile(
                    "mma.sync.aligned.m16n8k16.row.col.f32.bf16.bf16.f32 "
                    "{%0,%1,%2,%3}, {%4,%5,%6,%7}, {%8,%9}, {%0,%1,%2,%3};"
                    : "+f"(c1[0]), "+f"(c1[1]), "+f"(c1[2]), "+f"(c1[3])
                    : "r"(a[k][0]), "r"(a[k][1]), "r"(a[k][2]), "r"(a[k][3]),
                      "r"(b[k][2]), "r"(b[k][3]));
            }
            int colg = coltile + n0 + 2 * (lane & 3);
            ins4(c0[0], colg, tv[0], ti[0]);
            ins4(c0[1], colg + 1, tv[0], ti[0]);
            ins4(c0[2], colg, tv[1], ti[1]);
            ins4(c0[3], colg + 1, tv[1], ti[1]);
            ins4(c1[0], colg + 8, tv[0], ti[0]);
            ins4(c1[1], colg + 9, tv[0], ti[0]);
            ins4(c1[2], colg + 8, tv[1], ti[1]);
            ins4(c1[3], colg + 9, tv[1], ti[1]);
        }
        __syncthreads();
    }

    // write candidates: row covered by 8 threads (2 warps x 4 lanes)
    int rlo = row0 + m0 + (lane >> 2);
#pragma unroll
    for (int h = 0; h < 2; h++) {
        int row = rlo + h * 8;
        int base = row * 64 + split * 32 + (ch * 4 + (lane & 3)) * 4;
#pragma unroll
        for (int j = 0; j < 4; j++) g_cand[base + j] = ti[h][j];
    }
}

// ---------------------------------------------------------------------------
// kS: exact fp32 rescore of 64 candidates/row; 2 threads/row -> partial top-4s
// ---------------------------------------------------------------------------
__global__ __launch_bounds__(256) void kS()
{
    int gid = blockIdx.x * 256 + threadIdx.x;
    int n = gid >> 1, h = gid & 1;
    float4 qv[16];
#pragma unroll
    for (int i = 0; i < 16; i++) qv[i] = ((const float4*)&g_q[n * 64])[i];
    float tv[4]; int ti4[4];
#pragma unroll
    for (int j = 0; j < 4; j++) { tv[j] = -3.4e38f; ti4[j] = 0x7fffffff; }
    for (int c = 0; c < 32; c++) {
        int idx = g_cand[n * 64 + h * 32 + c];
        const float4* kp = (const float4*)&g_k[(size_t)idx * 64];
        float acc = 0.f;
#pragma unroll
        for (int i = 0; i < 16; i++) {
            float4 kv = kp[i];
            acc = fmaf(qv[i].x, kv.x, acc);
            acc = fmaf(qv[i].y, kv.y, acc);
            acc = fmaf(qv[i].z, kv.z, acc);
            acc = fmaf(qv[i].w, kv.w, acc);
        }
        ins4(acc, idx, tv, ti4);
    }
#pragma unroll
    for (int j = 0; j < 4; j++) {
        g_pv[n * 8 + h * 4 + j] = tv[j];
        g_pi[n * 8 + h * 4 + j] = ti4[j];
    }
}

// ---------------------------------------------------------------------------
// kM: merge the two partial top-4s per row
// ---------------------------------------------------------------------------
__global__ __launch_bounds__(256) void kM()
{
    int n = blockIdx.x * 256 + threadIdx.x;
    float bv[4]; int bi[4];
#pragma unroll
    for (int j = 0; j < 4; j++) { bv[j] = -3.4e38f; bi[j] = 0x7fffffff; }
#pragma unroll
    for (int p = 0; p < 8; p++) ins4(g_pv[n * 8 + p], g_pi[n * 8 + p], bv, bi);
#pragma unroll
    for (int j = 0; j < 4; j++) g_ctx[n * 4 + j] = bi[j];
}

// ---------------------------------------------------------------------------
// kP: precompute rule-combined time-conv matrices C[r][24][36]
// ---------------------------------------------------------------------------
__global__ void kP(
    const float* __restrict__ w_indiv, const float* __restrict__ w_social,
    const float* __restrict__ tp_w, const float* __restrict__ tp_b,
    const float* __restrict__ tpr_w, const float* __restrict__ tpr_b,
    const float* __restrict__ tpi_w, const float* __restrict__ tpi_b,
    const float* __restrict__ tpir_w, const float* __restrict__ tpir_b)
{
    int t = threadIdx.x;
    if (t >= 192) return;
    int r = t / 24, o2 = t % 24, o = o2 >> 1, pos = o2 & 1;
    float wi = w_indiv[r], ws = w_social[r];
    float* dst = g_C + (r * 24 + o2) * 36;
#pragma unroll
    for (int c = 0; c < 8; c++) {
        int wb = (r * 12 + o) * 8 + c;
        const float* wt = tpi_w + wb * 3;
        float wri = tpir_w[wb];
        float ci0 = pos == 0 ? (wt[1] + wri) : wt[0];
        float ci1 = pos == 0 ? wt[2] : (wt[1] + wri);
        dst[c] = wi * ci0;
        dst[8 + c] = wi * ci1;
        const float* ut = tp_w + wb * 3;
        float urs = tpr_w[wb];
        float cs0 = pos == 0 ? (ut[1] + urs) : ut[0];
        float cs1 = pos == 0 ? ut[2] : (ut[1] + urs);
        dst[16 + c] = ws * cs0;
        dst[24 + c] = ws * cs1;
    }
    dst[32] = wi * (tpi_b[r * 12 + o] + tpir_b[r * 12 + o])
            + ws * (tp_b[r * 12 + o] + tpr_b[r * 12 + o]);
    dst[33] = 0.f; dst[34] = 0.f; dst[35] = 0.f;
}

// ---------------------------------------------------------------------------
// kC: gather + selected-rule spatial convs + combined matvec. 8 nodes x 20 b.
// ---------------------------------------------------------------------------
__global__ __launch_bounds__(160) void kC(
    const float* __restrict__ obs_vel, const float* __restrict__ noise,
    const float* __restrict__ w_noise,
    const float* __restrict__ sp_w, const float* __restrict__ sp_b,
    const float* __restrict__ spr_w, const float* __restrict__ spr_b,
    const float* __restrict__ spi_w, const float* __restrict__ spi_b,
    const float* __restrict__ spir_w, const float* __restrict__ spir_b,
    float* __restrict__ out)
{
    __shared__ __align__(16) float s_C[8 * 24 * 36];
    __shared__ float s_sp_w[480], s_sp_b[16], s_spr_w[160], s_spr_b[16];
    __shared__ float s_spi_w[96], s_spi_b[16], s_spir_w[32], s_spir_b[16];
    __shared__ float s_wn[8], s_noise[BB * 2];
    __shared__ float s_ov[128], s_cvx[512];
    __shared__ int s_rule[8];

    int tid = threadIdx.x;
    int n0 = blockIdx.x * 8;

    for (int i = tid; i < 8 * 24 * 36; i += 160) s_C[i] = g_C[i];
    for (int i = tid; i < 480; i += 160) s_sp_w[i] = sp_w[i];
    for (int i = tid; i < 160; i += 160) s_spr_w[i] = spr_w[i];
    if (tid < 96) s_spi_w[tid] = spi_w[tid];
    if (tid < 32) s_spir_w[tid] = spir_w[tid];
    if (tid < 16) {
        s_sp_b[tid] = sp_b[tid]; s_spr_b[tid] = spr_b[tid];
        s_spi_b[tid] = spi_b[tid]; s_spir_b[tid] = spir_b[tid];
    }
    if (tid < 8) { s_wn[tid] = w_noise[tid]; s_rule[tid] = g_rule[n0 + tid]; }
    if (tid < 40) s_noise[tid] = noise[tid];
    for (int i = tid; i < 128; i += 160) {
        int node = i >> 4, s = (i >> 3) & 1, t = i & 7;
        s_ov[i] = obs_vel[s * NN * TT + (n0 + node) * TT + t];
    }
    for (int i = tid; i < 512; i += 160) {
        int node = i >> 6, rem = i & 63, k = rem >> 4, s = (rem >> 3) & 1, t = rem & 7;
        int nb = g_ctx[(n0 + node) * 4 + k];
        s_cvx[i] = obs_vel[s * NN * TT + nb * TT + t];
    }
    __syncthreads();

    int node = tid / 20, b = tid - node * 20;
    int n = n0 + node;
    int r = s_rule[node];
    float wn = s_wn[r];
    float nz0 = s_noise[b * 2 + 0] * wn;
    float nz1 = s_noise[b * 2 + 1] * wn;

    float v0[8], v1[8];
#pragma unroll
    for (int t = 0; t < 8; t++) {
        v0[t] = s_ov[node * 16 + t] + nz0;
        v1[t] = s_ov[node * 16 + 8 + t] + nz1;
    }

    float vals[32];

    {
        const float* pw3 = s_spi_w + r * 12;
        const float* pw1 = s_spir_w + r * 4;
#pragma unroll
        for (int so = 0; so < 2; so++) {
            float b3 = s_spi_b[r * 2 + so], b1 = s_spir_b[r * 2 + so];
            float w00 = pw3[so * 6 + 0], w01 = pw3[so * 6 + 1], w02 = pw3[so * 6 + 2];
            float w10 = pw3[so * 6 + 3], w11 = pw3[so * 6 + 4], w12 = pw3[so * 6 + 5];
            float wr0 = pw1[so * 2 + 0], wr1 = pw1[so * 2 + 1];
#pragma unroll
            for (int t = 0; t < 8; t++) {
                float a = b3;
                a = fmaf(w01, v0[t], a);
                a = fmaf(w11, v1[t], a);
                if (t > 0) { a = fmaf(w00, v0[t - 1], a); a = fmaf(w10, v1[t - 1], a); }
                if (t < 7) { a = fmaf(w02, v0[t + 1], a); a = fmaf(w12, v1[t + 1], a); }
                a = fmaxf(a, 0.f);
                float c1 = b1;
                c1 = fmaf(wr0, v0[t], c1);
                c1 = fmaf(wr1, v1[t], c1);
                vals[so * 8 + t] = a + c1;
            }
        }
    }

    {
        float a0[8], a1[8], c0[8], c1[8];
        float ba0 = s_sp_b[r * 2], ba1 = s_sp_b[r * 2 + 1];
        float bc0 = s_spr_b[r * 2], bc1 = s_spr_b[r * 2 + 1];
#pragma unroll
        for (int t = 0; t < 8; t++) { a0[t] = ba0; a1[t] = ba1; c0[t] = bc0; c1[t] = bc1; }
        const float* q3 = s_sp_w + r * 60;
        const float* q1 = s_spr_w + r * 20;

#define PROC_CH(ci, VV)                                                        \
        {                                                                      \
            float u0 = q3[(ci) * 3], u1 = q3[(ci) * 3 + 1], u2 = q3[(ci) * 3 + 2]; \
            float z0 = q3[30 + (ci) * 3], z1 = q3[30 + (ci) * 3 + 1], z2 = q3[30 + (ci) * 3 + 2]; \
            float ur = q1[(ci)], zr = q1[10 + (ci)];                           \
            _Pragma("unroll")                                                  \
            for (int t = 0; t < 8; t++) {                                      \
                float x = VV[t];                                               \
                a0[t] = fmaf(u1, x, a0[t]); a1[t] = fmaf(z1, x, a1[t]);        \
                c0[t] = fmaf(ur, x, c0[t]); c1[t] = fmaf(zr, x, c1[t]);        \
                if (t > 0) { a0[t] = fmaf(u0, VV[t - 1], a0[t]); a1[t] = fmaf(z0, VV[t - 1], a1[t]); } \
                if (t < 7) { a0[t] = fmaf(u2, VV[t + 1], a0[t]); a1[t] = fmaf(z2, VV[t + 1], a1[t]); } \
            }                                                                  \
        }

        PROC_CH(0, v0)
        PROC_CH(1, v1)
#pragma unroll
        for (int k = 0; k < 4; k++) {
            float nb0[8], nb1[8];
#pragma unroll
            for (int t = 0; t < 8; t++) {
                nb0[t] = s_cvx[node * 64 + k * 16 + t] + nz0;
                nb1[t] = s_cvx[node * 64 + k * 16 + 8 + t] + nz1;
            }
            PROC_CH(2 + k * 2 + 0, nb0)
            PROC_CH(2 + k * 2 + 1, nb1)
        }
#undef PROC_CH
#pragma unroll
        for (int t = 0; t < 8; t++) {
            vals[16 + t] = fmaxf(a0[t], 0.f) + c0[t];
            vals[24 + t] = fmaxf(a1[t], 0.f) + c1[t];
        }
    }

    ull pk[16];
#pragma unroll
    for (int p = 0; p < 16; p++) pk[p] = pack2(vals[2 * p], vals[2 * p + 1]);

    const float* Cb = s_C + r * 24 * 36;
    float* outp = out + ((size_t)b * NN + n) * 24;
#pragma unroll 4
    for (int o2 = 0; o2 < 24; o2++) {
        const ulonglong2* cp = (const ulonglong2*)(Cb + o2 * 36);
        ull acc = pack2(Cb[o2 * 36 + 32], 0.f);
#pragma unroll
        for (int p = 0; p < 8; p++) {
            ulonglong2 cc = cp[p];
            acc = fma2(cc.x, pk[2 * p], acc);
            acc = fma2(cc.y, pk[2 * p + 1], acc);
        }
        float lo, hi;
        unpack2(acc, lo, hi);
        outp[o2] = lo + hi;
    }
}

// ---------------------------------------------------------------------------
extern "C" void kernel_launch(void* const* d_in, const int* in_sizes, int n_in,
                              void* d_out, int out_size)
{
    const float* obs      = (const float*)d_in[0];
    const float* obs_vel  = (const float*)d_in[1];
    const float* noise    = (const float*)d_in[2];
    const float* wq_rule  = (const float*)d_in[3];
    const float* bq_rule  = (const float*)d_in[4];
    const float* wq_ctx   = (const float*)d_in[5];
    const float* bq_ctx   = (const float*)d_in[6];
    const float* wk_ctx   = (const float*)d_in[7];
    const float* bk_ctx   = (const float*)d_in[8];
    const float* rule_emb = (const float*)d_in[9];
    const float* w_noise  = (const float*)d_in[10];
    const float* w_indiv  = (const float*)d_in[11];
    const float* w_social = (const float*)d_in[12];
    const float* sp_w  = (const float*)d_in[13];
    const float* sp_b  = (const float*)d_in[14];
    const float* spr_w = (const float*)d_in[15];
    const float* spr_b = (const float*)d_in[16];
    const float* tp_w  = (const float*)d_in[17];
    const float* tp_b  = (const float*)d_in[18];
    const float* tpr_w = (const float*)d_in[19];
    const float* tpr_b = (const float*)d_in[20];
    const float* spi_w  = (const float*)d_in[21];
    const float* spi_b  = (const float*)d_in[22];
    const float* spir_w = (const float*)d_in[23];
    const float* spir_b = (const float*)d_in[24];
    const float* tpi_w  = (const float*)d_in[25];
    const float* tpi_b  = (const float*)d_in[26];
    const float* tpir_w = (const float*)d_in[27];
    const float* tpir_b = (const float*)d_in[28];
    float* out = (float*)d_out;

    static bool attr_set = false;
    if (!attr_set) {
        cudaFuncSetAttribute(kB_hmma, cudaFuncAttributeMaxDynamicSharedMemorySize, 73728);
        attr_set = true;
    }

    kA<<<64, 256>>>(obs, obs_vel, wq_rule, bq_rule, wq_ctx, bq_ctx, wk_ctx, bk_ctx);
    kR<<<32, 128>>>(rule_emb);
    kP<<<1, 192>>>(w_indiv, w_social, tp_w, tp_b, tpr_w, tpr_b,
                   tpi_w, tpi_b, tpir_w, tpir_b);
    kB_hmma<<<dim3(64, 2), 256, 73728>>>();
    kS<<<32, 256>>>();
    kM<<<16, 256>>>();
    kC<<<512, 160>>>(obs_vel, noise, w_noise,
                     sp_w, sp_b, spr_w, spr_b,
                     spi_w, spi_b, spir_w, spir_b, out);
}

// round 6
// speedup vs baseline: 2.1410x; 1.2594x over previous
#include <cuda_runtime.h>
#include <cuda_bf16.h>
#include <cstdint>

#define NN 4096
#define TT 8
#define KTOP 4
#define RR 8
#define DKK 64
#define BB 20

typedef unsigned long long ull;

__device__ __align__(16) float g_q[NN * DKK];
__device__ __align__(16) float g_k[NN * DKK];
__device__ __align__(16) float g_rq[NN * DKK];
__device__ __align__(16) __nv_bfloat16 g_qh[NN * DKK];
__device__ __align__(16) __nv_bfloat16 g_kh[NN * DKK];
__device__ __align__(16) float g_C[RR * 24 * 36];
__device__ __align__(16) int g_cand[NN * 128];
__device__ int g_ctx[NN * KTOP];
__device__ int g_rule[NN];

// ---------------- small helpers ----------------
__device__ __forceinline__ ull pack2(float a, float b) {
    ull r;
    asm("mov.b64 %0, {%1, %2};" : "=l"(r) : "f"(a), "f"(b));
    return r;
}
__device__ __forceinline__ void unpack2(ull v, float& a, float& b) {
    asm("mov.b64 {%0, %1}, %2;" : "=f"(a), "=f"(b) : "l"(v));
}
__device__ __forceinline__ ull fma2(ull a, ull b, ull c) {
    ull d;
    asm("fma.rn.f32x2 %0, %1, %2, %3;" : "=l"(d) : "l"(a), "l"(b), "l"(c));
    return d;
}
__device__ __forceinline__ void ins4(float v, int idx, float* tv, int* ti) {
    if (v > tv[3] || (v == tv[3] && idx < ti[3])) {
        tv[3] = v; ti[3] = idx;
#pragma unroll
        for (int j = 3; j > 0; j--) {
            bool sw = (tv[j] > tv[j - 1]) || (tv[j] == tv[j - 1] && ti[j] < ti[j - 1]);
            if (sw) {
                float f = tv[j]; tv[j] = tv[j - 1]; tv[j - 1] = f;
                int q = ti[j]; ti[j] = ti[j - 1]; ti[j - 1] = q;
            }
        }
    }
}
__device__ __forceinline__ uint32_t smem_to_u32(const void* p) {
    uint32_t a;
    asm("{ .reg .u64 t; cvta.to.shared.u64 t, %1; cvt.u32.u64 %0, t; }" : "=r"(a) : "l"(p));
    return a;
}
// XOR swizzle: rows of 128B, 16B chunks permuted by row
#define SWZ(row, byteoff) \
    ((row) * 128 + (((((byteoff) >> 4) ^ ((row) & 7)) << 4)) + ((byteoff) & 15))

// ---------------------------------------------------------------------------
// kA: x[4096x32] @ W[32x192] -> g_q | g_k | g_rq, plus bf16 copies of q,k
// ---------------------------------------------------------------------------
__global__ __launch_bounds__(256) void kA(
    const float* __restrict__ obs, const float* __restrict__ obs_vel,
    const float* __restrict__ wq_rule, const float* __restrict__ bq_rule,
    const float* __restrict__ wq_ctx, const float* __restrict__ bq_ctx,
    const float* __restrict__ wk_ctx, const float* __restrict__ bk_ctx)
{
    __shared__ __align__(16) ull x2_s[32 * 64];
    __shared__ __align__(16) ull w_s[32 * 96];
    int tid = threadIdx.x;
    int n0 = blockIdx.x * 64;

    float* xf = (float*)x2_s;
    for (int e = tid; e < 32 * 64; e += 256) {
        int i = e >> 6, node = e & 63;
        int t = i >> 2, c = i & 3;
        const float* src = (c < 2) ? obs : obs_vel;
        float v = src[(c & 1) * NN * TT + (n0 + node) * TT + t];
        xf[e * 2] = v; xf[e * 2 + 1] = v;
    }
    float* wf = (float*)w_s;
    for (int e = tid; e < 32 * 192; e += 256) {
        int i = e / 192, col = e % 192;
        float v;
        if (col < 64) v = wq_ctx[i * 64 + col];
        else if (col < 128) v = wk_ctx[i * 64 + col - 64];
        else {
            int c = i & 3;
            if (c >= 2) v = wq_rule[((i >> 2) * 2 + (c - 2)) * 64 + (col - 128)];
            else v = 0.f;
        }
        wf[i * 192 + col] = v;
    }
    __syncthreads();

    int w = tid >> 5, tx = tid & 31;
    int rbase = w * 8;
    ull bp[3];
#pragma unroll
    for (int j = 0; j < 3; j++) {
        int c2 = (tx * 3 + j) * 2;
        float b0, b1;
        if (c2 < 64) { b0 = bq_ctx[c2]; b1 = bq_ctx[c2 + 1]; }
        else if (c2 < 128) { b0 = bk_ctx[c2 - 64]; b1 = bk_ctx[c2 - 63]; }
        else { b0 = bq_rule[c2 - 128]; b1 = bq_rule[c2 - 127]; }
        bp[j] = pack2(b0, b1);
    }
    ull acc[8][3];
#pragma unroll
    for (int r = 0; r < 8; r++)
#pragma unroll
        for (int j = 0; j < 3; j++) acc[r][j] = bp[j];

#pragma unroll 8
    for (int kk = 0; kk < 32; kk++) {
        const ulonglong2* qp = (const ulonglong2*)(x2_s + kk * 64 + rbase);
        ulonglong2 q0 = qp[0], q1 = qp[1], q2v = qp[2], q3 = qp[3];
        ull qr[8] = { q0.x, q0.y, q1.x, q1.y, q2v.x, q2v.y, q3.x, q3.y };
        ull wv0 = w_s[kk * 96 + tx * 3 + 0];
        ull wv1 = w_s[kk * 96 + tx * 3 + 1];
        ull wv2 = w_s[kk * 96 + tx * 3 + 2];
#pragma unroll
        for (int r = 0; r < 8; r++) {
            acc[r][0] = fma2(qr[r], wv0, acc[r][0]);
            acc[r][1] = fma2(qr[r], wv1, acc[r][1]);
            acc[r][2] = fma2(qr[r], wv2, acc[r][2]);
        }
    }
#pragma unroll
    for (int r = 0; r < 8; r++) {
        int node = n0 + rbase + r;
#pragma unroll
        for (int j = 0; j < 3; j++) {
            int c2 = (tx * 3 + j) * 2;
            float v0, v1;
            unpack2(acc[r][j], v0, v1);
            int cc = c2 & 63;
            if (c2 < 64) {
                g_q[node * 64 + cc] = v0;
                g_q[node * 64 + cc + 1] = v1;
                *(__nv_bfloat162*)&g_qh[node * 64 + cc] = __floats2bfloat162_rn(v0, v1);
            } else if (c2 < 128) {
                g_k[node * 64 + cc] = v0;
                g_k[node * 64 + cc + 1] = v1;
                *(__nv_bfloat162*)&g_kh[node * 64 + cc] = __floats2bfloat162_rn(v0, v1);
            } else {
                g_rq[node * 64 + cc] = v0;
                g_rq[node * 64 + cc + 1] = v1;
            }
        }
    }
}

// ---------------------------------------------------------------------------
// kR: rule argmax from g_rq @ rule_emb^T
// ---------------------------------------------------------------------------
__global__ __launch_bounds__(128) void kR(const float* __restrict__ rule_emb)
{
    __shared__ float s_emb[64 * 8];
    int tid = threadIdx.x;
    for (int e = tid; e < 512; e += 128) s_emb[e] = rule_emb[(e & 7) * 64 + (e >> 3)];
    __syncthreads();
    int n = blockIdx.x * 128 + tid;
    float lg[8];
#pragma unroll
    for (int r = 0; r < 8; r++) lg[r] = 0.f;
#pragma unroll
    for (int og = 0; og < 16; og++) {
        float4 v = *(const float4*)&g_rq[n * 64 + og * 4];
        float vv[4] = { v.x, v.y, v.z, v.w };
#pragma unroll
        for (int e = 0; e < 4; e++) {
            int o = og * 4 + e;
#pragma unroll
            for (int r = 0; r < 8; r++) lg[r] = fmaf(vv[e], s_emb[o * 8 + r], lg[r]);
        }
    }
    int best = 0;
    float bv = lg[0];
#pragma unroll
    for (int r = 1; r < 8; r++)
        if (lg[r] > bv) { bv = lg[r]; best = r; }
    g_rule[n] = best;
}

// ---------------------------------------------------------------------------
// kB_hmma: scores via mma.sync bf16 HMMA + per-thread top-4 candidates.
// grid (128 rowblocks, 2 colsplits) x 256 thr, 2 CTAs/SM -> 256 CTAs.
// CTA: 32 rows x 2048 cols, K=64. Warp = 16 rows (rg) x 64 cols (ch) per
// 256-col tile; np loop of 4.
// smem: A 4KB + B 2x32KB (double-buffered cp.async) = 68KB dynamic.
// Candidates: 16 threads/row x top-4 = 64 per row per split -> g_cand[*128].
// ---------------------------------------------------------------------------
__global__ __launch_bounds__(256, 2) void kB_hmma()
{
    extern __shared__ char smem[];
    char* As = smem;               // 32 x 128B
    char* Bs0 = smem + 4096;       // 256 x 128B
    char* Bs1 = smem + 4096 + 32768;
    int tid = threadIdx.x, lane = tid & 31, wid = tid >> 5;
    int row0 = blockIdx.x * 32;
    int split = blockIdx.y;
    int colbase = split * 2048;

    // stage A (swizzled): 32 rows x 8 chunks = 256
    {
        int r = tid >> 3, c = tid & 7;
        uint4 v = *(const uint4*)((const char*)g_qh + (size_t)(row0 + r) * 128 + c * 16);
        *(uint4*)(As + r * 128 + ((c ^ (r & 7)) << 4)) = v;
    }
    // prefetch B tile 0
    {
        int r = tid;
        const char* src = (const char*)g_kh + (size_t)(colbase + r) * 128;
        char* dst = Bs0 + r * 128;
#pragma unroll
        for (int c = 0; c < 8; c++) {
            uint32_t daddr = smem_to_u32(dst + ((c ^ (r & 7)) << 4));
            asm volatile("cp.async.cg.shared.global [%0], [%1], 16;"
                         :: "r"(daddr), "l"(src + c * 16));
        }
        asm volatile("cp.async.commit_group;");
    }
    __syncthreads();

    int rg = wid >> 2, ch = wid & 3;
    int m0 = rg * 16;

    // A fragments: a[k][0..3] for 4 k-steps of 16
    uint32_t a[4][4];
    {
        int arow = m0 + (lane & 15);
        int kbh = ((lane >> 4) & 1) * 16;
#pragma unroll
        for (int k = 0; k < 4; k++) {
            int byteoff = k * 32 + kbh;
            uint32_t addr = smem_to_u32(As + SWZ(arow, byteoff));
            asm volatile("ldmatrix.sync.aligned.m8n8.x4.shared.b16 {%0,%1,%2,%3}, [%4];"
                : "=r"(a[k][0]), "=r"(a[k][1]), "=r"(a[k][2]), "=r"(a[k][3]) : "r"(addr));
        }
    }

    int brow_off = (lane & 7) + ((lane & 16) >> 1);
    int bkb = (lane & 8) ? 16 : 0;

    float tv[2][4];
    int ti[2][4];
#pragma unroll
    for (int h = 0; h < 2; h++)
#pragma unroll
        for (int j = 0; j < 4; j++) { tv[h][j] = -3.4e38f; ti[h][j] = 0x7fffffff; }

    for (int t = 0; t < 8; t++) {
        if (t < 7) {
            char* dst0 = ((t + 1) & 1) ? Bs1 : Bs0;
            int r = tid;
            const char* src = (const char*)g_kh + (size_t)(colbase + (t + 1) * 256 + r) * 128;
            char* dst = dst0 + r * 128;
#pragma unroll
            for (int c = 0; c < 8; c++) {
                uint32_t daddr = smem_to_u32(dst + ((c ^ (r & 7)) << 4));
                asm volatile("cp.async.cg.shared.global [%0], [%1], 16;"
                             :: "r"(daddr), "l"(src + c * 16));
            }
            asm volatile("cp.async.commit_group;");
            asm volatile("cp.async.wait_group 1;");
        } else {
            asm volatile("cp.async.wait_group 0;");
        }
        __syncthreads();

        const char* B = (t & 1) ? Bs1 : Bs0;
        int coltile = colbase + t * 256;
#pragma unroll
        for (int np = 0; np < 4; np++) {
            int n0 = ch * 64 + np * 16;
            uint32_t b[4][4];
#pragma unroll
            for (int k = 0; k < 4; k++) {
                int brow = n0 + brow_off;
                int byteoff = k * 32 + bkb;
                uint32_t addr = smem_to_u32(B + SWZ(brow, byteoff));
                asm volatile("ldmatrix.sync.aligned.m8n8.x4.shared.b16 {%0,%1,%2,%3}, [%4];"
                    : "=r"(b[k][0]), "=r"(b[k][1]), "=r"(b[k][2]), "=r"(b[k][3]) : "r"(addr));
            }
            float c0[4] = {0.f, 0.f, 0.f, 0.f};
            float c1[4] = {0.f, 0.f, 0.f, 0.f};
#pragma unroll
            for (int k = 0; k < 4; k++) {
                asm volatile(
                    "mma.sync.aligned.m16n8k16.row.col.f32.bf16.bf16.f32 "
                    "{%0,%1,%2,%3}, {%4,%5,%6,%7}, {%8,%9}, {%0,%1,%2,%3};"
                    : "+f"(c0[0]), "+f"(c0[1]), "+f"(c0[2]), "+f"(c0[3])
                    : "r"(a[k][0]), "r"(a[k][1]), "r"(a[k][2]), "r"(a[k][3]),
                      "r"(b[k][0]), "r"(b[k][1]));
                asm volatile(
                    "mma.sync.aligned.m16n8k16.row.col.f32.bf16.bf16.f32 "
                    "{%0,%1,%2,%3}, {%4,%5,%6,%7}, {%8,%9}, {%0,%1,%2,%3};"
                    : "+f"(c1[0]), "+f"(c1[1]), "+f"(c1[2]), "+f"(c1[3])
                    : "r"(a[k][0]), "r"(a[k][1]), "r"(a[k][2]), "r"(a[k][3]),
                      "r"(b[k][2]), "r"(b[k][3]));
            }
            int colg = coltile + n0 + 2 * (lane & 3);
            // row-half 0 (rows lane>>2): c0[0],c0[1],c1[0],c1[1]
            float m0v = fmaxf(fmaxf(c0[0], c0[1]), fmaxf(c1[0], c1[1]));
            if (m0v >= tv[0][3]) {
                ins4(c0[0], colg, tv[0], ti[0]);
                ins4(c0[1], colg + 1, tv[0], ti[0]);
                ins4(c1[0], colg + 8, tv[0], ti[0]);
                ins4(c1[1], colg + 9, tv[0], ti[0]);
            }
            // row-half 1 (rows lane>>2 + 8): c0[2],c0[3],c1[2],c1[3]
            float m1v = fmaxf(fmaxf(c0[2], c0[3]), fmaxf(c1[2], c1[3]));
            if (m1v >= tv[1][3]) {
                ins4(c0[2], colg, tv[1], ti[1]);
                ins4(c0[3], colg + 1, tv[1], ti[1]);
                ins4(c1[2], colg + 8, tv[1], ti[1]);
                ins4(c1[3], colg + 9, tv[1], ti[1]);
            }
        }
        __syncthreads();
    }

    // write candidates: each row covered by 16 threads (4 ch-warps x 4 lanes)
    int slot = ch * 4 + (lane & 3);
    int rlo = row0 + m0 + (lane >> 2);
#pragma unroll
    for (int h = 0; h < 2; h++) {
        int row = rlo + h * 8;
        int base = row * 128 + split * 64 + slot * 4;
#pragma unroll
        for (int j = 0; j < 4; j++) g_cand[base + j] = ti[h][j];
    }
}

// ---------------------------------------------------------------------------
// kS: exact fp32 rescore of 128 candidates/row. Warp per row; each lane does
// 4 candidates, scores to smem, lane 0 does tie-correct top-4 -> g_ctx.
// ---------------------------------------------------------------------------
__global__ __launch_bounds__(256) void kS()
{
    __shared__ float sv[8 * 128];
    __shared__ int si[8 * 128];
    int tid = threadIdx.x, lane = tid & 31, wid = tid >> 5;
    int row = blockIdx.x * 8 + wid;

    // lane-uniform q loads (broadcast)
    float4 qv[16];
    const float4* qp = (const float4*)&g_q[row * 64];
#pragma unroll
    for (int i = 0; i < 16; i++) qv[i] = qp[i];

    int4 ci = ((const int4*)&g_cand[row * 128])[lane];
    int idxs[4] = { ci.x, ci.y, ci.z, ci.w };
#pragma unroll
    for (int j = 0; j < 4; j++) {
        int idx = idxs[j];
        const float4* kp = (const float4*)&g_k[(size_t)idx * 64];
        float acc = 0.f;
#pragma unroll
        for (int i = 0; i < 16; i++) {
            float4 kv = kp[i];
            acc = fmaf(qv[i].x, kv.x, acc);
            acc = fmaf(qv[i].y, kv.y, acc);
            acc = fmaf(qv[i].z, kv.z, acc);
            acc = fmaf(qv[i].w, kv.w, acc);
        }
        sv[wid * 128 + lane * 4 + j] = acc;
        si[wid * 128 + lane * 4 + j] = idx;
    }
    __syncwarp(0xffffffff);
    if (lane == 0) {
        float tv[4]; int ti4[4];
#pragma unroll
        for (int j = 0; j < 4; j++) { tv[j] = -3.4e38f; ti4[j] = 0x7fffffff; }
        for (int p = 0; p < 128; p++) ins4(sv[wid * 128 + p], si[wid * 128 + p], tv, ti4);
#pragma unroll
        for (int j = 0; j < 4; j++) g_ctx[row * 4 + j] = ti4[j];
    }
}

// ---------------------------------------------------------------------------
// kP: precompute rule-combined time-conv matrices C[r][24][36]
// ---------------------------------------------------------------------------
__global__ void kP(
    const float* __restrict__ w_indiv, const float* __restrict__ w_social,
    const float* __restrict__ tp_w, const float* __restrict__ tp_b,
    const float* __restrict__ tpr_w, const float* __restrict__ tpr_b,
    const float* __restrict__ tpi_w, const float* __restrict__ tpi_b,
    const float* __restrict__ tpir_w, const float* __restrict__ tpir_b)
{
    int t = threadIdx.x;
    if (t >= 192) return;
    int r = t / 24, o2 = t % 24, o = o2 >> 1, pos = o2 & 1;
    float wi = w_indiv[r], ws = w_social[r];
    float* dst = g_C + (r * 24 + o2) * 36;
#pragma unroll
    for (int c = 0; c < 8; c++) {
        int wb = (r * 12 + o) * 8 + c;
        const float* wt = tpi_w + wb * 3;
        float wri = tpir_w[wb];
        float ci0 = pos == 0 ? (wt[1] + wri) : wt[0];
        float ci1 = pos == 0 ? wt[2] : (wt[1] + wri);
        dst[c] = wi * ci0;
        dst[8 + c] = wi * ci1;
        const float* ut = tp_w + wb * 3;
        float urs = tpr_w[wb];
        float cs0 = pos == 0 ? (ut[1] + urs) : ut[0];
        float cs1 = pos == 0 ? ut[2] : (ut[1] + urs);
        dst[16 + c] = ws * cs0;
        dst[24 + c] = ws * cs1;
    }
    dst[32] = wi * (tpi_b[r * 12 + o] + tpir_b[r * 12 + o])
            + ws * (tp_b[r * 12 + o] + tpr_b[r * 12 + o]);
    dst[33] = 0.f; dst[34] = 0.f; dst[35] = 0.f;
}

// ---------------------------------------------------------------------------
// kC: gather + selected-rule spatial convs + combined matvec. 16 nodes x 20 b.
// ---------------------------------------------------------------------------
__global__ __launch_bounds__(320) void kC(
    const float* __restrict__ obs_vel, const float* __restrict__ noise,
    const float* __restrict__ w_noise,
    const float* __restrict__ sp_w, const float* __restrict__ sp_b,
    const float* __restrict__ spr_w, const float* __restrict__ spr_b,
    const float* __restrict__ spi_w, const float* __restrict__ spi_b,
    const float* __restrict__ spir_w, const float* __restrict__ spir_b,
    float* __restrict__ out)
{
    __shared__ __align__(16) float s_C[8 * 24 * 36];
    __shared__ float s_sp_w[480], s_sp_b[16], s_spr_w[160], s_spr_b[16];
    __shared__ float s_spi_w[96], s_spi_b[16], s_spir_w[32], s_spir_b[16];
    __shared__ float s_wn[8], s_noise[BB * 2];
    __shared__ float s_ov[256], s_cvx[1024];
    __shared__ int s_rule[16];

    int tid = threadIdx.x;
    int n0 = blockIdx.x * 16;

    for (int i = tid; i < 8 * 24 * 36; i += 320) s_C[i] = g_C[i];
    for (int i = tid; i < 480; i += 320) s_sp_w[i] = sp_w[i];
    if (tid < 160) s_spr_w[tid] = spr_w[tid];
    if (tid < 96) s_spi_w[tid] = spi_w[tid];
    if (tid < 32) s_spir_w[tid] = spir_w[tid];
    if (tid < 16) {
        s_sp_b[tid] = sp_b[tid]; s_spr_b[tid] = spr_b[tid];
        s_spi_b[tid] = spi_b[tid]; s_spir_b[tid] = spir_b[tid];
        s_rule[tid] = g_rule[n0 + tid];
    }
    if (tid < 8) s_wn[tid] = w_noise[tid];
    if (tid < 40) s_noise[tid] = noise[tid];
    for (int i = tid; i < 256; i += 320) {
        int node = i >> 4, s = (i >> 3) & 1, t = i & 7;
        s_ov[i] = obs_vel[s * NN * TT + (n0 + node) * TT + t];
    }
    for (int i = tid; i < 1024; i += 320) {
        int node = i >> 6, rem = i & 63, k = rem >> 4, s = (rem >> 3) & 1, t = rem & 7;
        int nb = g_ctx[(n0 + node) * 4 + k];
        s_cvx[i] = obs_vel[s * NN * TT + nb * TT + t];
    }
    __syncthreads();

    int node = tid / 20, b = tid - node * 20;
    int n = n0 + node;
    int r = s_rule[node];
    float wn = s_wn[r];
    float nz0 = s_noise[b * 2 + 0] * wn;
    float nz1 = s_noise[b * 2 + 1] * wn;

    float v0[8], v1[8];
#pragma unroll
    for (int t = 0; t < 8; t++) {
        v0[t] = s_ov[node * 16 + t] + nz0;
        v1[t] = s_ov[node * 16 + 8 + t] + nz1;
    }

    float vals[32];

    {
        const float* pw3 = s_spi_w + r * 12;
        const float* pw1 = s_spir_w + r * 4;
#pragma unroll
        for (int so = 0; so < 2; so++) {
            float b3 = s_spi_b[r * 2 + so], b1 = s_spir_b[r * 2 + so];
            float w00 = pw3[so * 6 + 0], w01 = pw3[so * 6 + 1], w02 = pw3[so * 6 + 2];
            float w10 = pw3[so * 6 + 3], w11 = pw3[so * 6 + 4], w12 = pw3[so * 6 + 5];
            float wr0 = pw1[so * 2 + 0], wr1 = pw1[so * 2 + 1];
#pragma unroll
            for (int t = 0; t < 8; t++) {
                float a = b3;
                a = fmaf(w01, v0[t], a);
                a = fmaf(w11, v1[t], a);
                if (t > 0) { a = fmaf(w00, v0[t - 1], a); a = fmaf(w10, v1[t - 1], a); }
                if (t < 7) { a = fmaf(w02, v0[t + 1], a); a = fmaf(w12, v1[t + 1], a); }
                a = fmaxf(a, 0.f);
                float c1 = b1;
                c1 = fmaf(wr0, v0[t], c1);
                c1 = fmaf(wr1, v1[t], c1);
                vals[so * 8 + t] = a + c1;
            }
        }
    }

    {
        float a0[8], a1[8], c0[8], c1[8];
        float ba0 = s_sp_b[r * 2], ba1 = s_sp_b[r * 2 + 1];
        float bc0 = s_spr_b[r * 2], bc1 = s_spr_b[r * 2 + 1];
#pragma unroll
        for (int t = 0; t < 8; t++) { a0[t] = ba0; a1[t] = ba1; c0[t] = bc0; c1[t] = bc1; }
        const float* q3 = s_sp_w + r * 60;
        const float* q1 = s_spr_w + r * 20;

#define PROC_CH(ci, VV)                                                        \
        {                                                                      \
            float u0 = q3[(ci) * 3], u1 = q3[(ci) * 3 + 1], u2 = q3[(ci) * 3 + 2]; \
            float z0 = q3[30 + (ci) * 3], z1 = q3[30 + (ci) * 3 + 1], z2 = q3[30 + (ci) * 3 + 2]; \
            float ur = q1[(ci)], zr = q1[10 + (ci)];                           \
            _Pragma("unroll")                                                  \
            for (int t = 0; t < 8; t++) {                                      \
                float x = VV[t];                                               \
                a0[t] = fmaf(u1, x, a0[t]); a1[t] = fmaf(z1, x, a1[t]);        \
                c0[t] = fmaf(ur, x, c0[t]); c1[t] = fmaf(zr, x, c1[t]);        \
                if (t > 0) { a0[t] = fmaf(u0, VV[t - 1], a0[t]); a1[t] = fmaf(z0, VV[t - 1], a1[t]); } \
                if (t < 7) { a0[t] = fmaf(u2, VV[t + 1], a0[t]); a1[t] = fmaf(z2, VV[t + 1], a1[t]); } \
            }                                                                  \
        }

        PROC_CH(0, v0)
        PROC_CH(1, v1)
#pragma unroll
        for (int k = 0; k < 4; k++) {
            float nb0[8], nb1[8];
#pragma unroll
            for (int t = 0; t < 8; t++) {
                nb0[t] = s_cvx[node * 64 + k * 16 + t] + nz0;
                nb1[t] = s_cvx[node * 64 + k * 16 + 8 + t] + nz1;
            }
            PROC_CH(2 + k * 2 + 0, nb0)
            PROC_CH(2 + k * 2 + 1, nb1)
        }
#undef PROC_CH
#pragma unroll
        for (int t = 0; t < 8; t++) {
            vals[16 + t] = fmaxf(a0[t], 0.f) + c0[t];
            vals[24 + t] = fmaxf(a1[t], 0.f) + c1[t];
        }
    }

    ull pk[16];
#pragma unroll
    for (int p = 0; p < 16; p++) pk[p] = pack2(vals[2 * p], vals[2 * p + 1]);

    const float* Cb = s_C + r * 24 * 36;
    float* outp = out + ((size_t)b * NN + n) * 24;
#pragma unroll 4
    for (int o2 = 0; o2 < 24; o2++) {
        const ulonglong2* cp = (const ulonglong2*)(Cb + o2 * 36);
        ull acc = pack2(Cb[o2 * 36 + 32], 0.f);
#pragma unroll
        for (int p = 0; p < 8; p++) {
            ulonglong2 cc = cp[p];
            acc = fma2(cc.x, pk[2 * p], acc);
            acc = fma2(cc.y, pk[2 * p + 1], acc);
        }
        float lo, hi;
        unpack2(acc, lo, hi);
        outp[o2] = lo + hi;
    }
}

// ---------------------------------------------------------------------------
extern "C" void kernel_launch(void* const* d_in, const int* in_sizes, int n_in,
                              void* d_out, int out_size)
{
    const float* obs      = (const float*)d_in[0];
    const float* obs_vel  = (const float*)d_in[1];
    const float* noise    = (const float*)d_in[2];
    const float* wq_rule  = (const float*)d_in[3];
    const float* bq_rule  = (const float*)d_in[4];
    const float* wq_ctx   = (const float*)d_in[5];
    const float* bq_ctx   = (const float*)d_in[6];
    const float* wk_ctx   = (const float*)d_in[7];
    const float* bk_ctx   = (const float*)d_in[8];
    const float* rule_emb = (const float*)d_in[9];
    const float* w_noise  = (const float*)d_in[10];
    const float* w_indiv  = (const float*)d_in[11];
    const float* w_social = (const float*)d_in[12];
    const float* sp_w  = (const float*)d_in[13];
    const float* sp_b  = (const float*)d_in[14];
    const float* spr_w = (const float*)d_in[15];
    const float* spr_b = (const float*)d_in[16];
    const float* tp_w  = (const float*)d_in[17];
    const float* tp_b  = (const float*)d_in[18];
    const float* tpr_w = (const float*)d_in[19];
    const float* tpr_b = (const float*)d_in[20];
    const float* spi_w  = (const float*)d_in[21];
    const float* spi_b  = (const float*)d_in[22];
    const float* spir_w = (const float*)d_in[23];
    const float* spir_b = (const float*)d_in[24];
    const float* tpi_w  = (const float*)d_in[25];
    const float* tpi_b  = (const float*)d_in[26];
    const float* tpir_w = (const float*)d_in[27];
    const float* tpir_b = (const float*)d_in[28];
    float* out = (float*)d_out;

    static bool attr_set = false;
    if (!attr_set) {
        cudaFuncSetAttribute(kB_hmma, cudaFuncAttributeMaxDynamicSharedMemorySize, 69632);
        attr_set = true;
    }

    kA<<<64, 256>>>(obs, obs_vel, wq_rule, bq_rule, wq_ctx, bq_ctx, wk_ctx, bk_ctx);
    kR<<<32, 128>>>(rule_emb);
    kP<<<1, 192>>>(w_indiv, w_social, tp_w, tp_b, tpr_w, tpr_b,
                   tpi_w, tpi_b, tpir_w, tpir_b);
    kB_hmma<<<dim3(128, 2), 256, 69632>>>();
    kS<<<512, 256>>>();
    kC<<<256, 320>>>(obs_vel, noise, w_noise,
                     sp_w, sp_b, spr_w, spr_b,
                     spi_w, spi_b, spir_w, spir_b, out);
}